// round 5
// baseline (speedup 1.0000x reference)
#include <cuda_runtime.h>
#include <cuda_bf16.h>
#include <math.h>

// Problem constants (Qwen3-MoE decoder layer)
constexpr int T_   = 2048;
constexpr int D_   = 2048;
constexpr int NQ_  = 16;
constexpr int NKV_ = 4;
constexpr int H_   = 128;
constexpr int E_   = 16;
constexpr int F_   = 1024;
constexpr int NPAIR_ = T_ * 4;   // token * top_k slots

// ---------------- scratch (static device globals; no allocation) -------------
__device__ float g_hnorm[T_ * D_];
__device__ float g_q[T_ * NQ_ * H_];
__device__ float g_k[T_ * NKV_ * H_];
__device__ float g_v[T_ * NKV_ * H_];
__device__ float g_attn[T_ * NQ_ * H_];
__device__ float g_h1[T_ * D_];
__device__ float g_h2[T_ * D_];
__device__ float g_gu[(size_t)NPAIR_ * 2 * F_];   // gate_up raw out; first F cols reused as act
__device__ float g_part[(size_t)NPAIR_ * D_];     // per-slot expert out (64 MB)
__device__ float g_wgt[NPAIR_];
__device__ int   g_cnt[E_];
__device__ int   g_list[E_ * T_];

// ---------------- RMSNorm over rows of length D_ ------------------------------
__global__ __launch_bounds__(256) void rmsnorm_k(const float* __restrict__ x,
                                                 const float* __restrict__ w,
                                                 float* __restrict__ y) {
    int row = blockIdx.x;
    const float4* xr = (const float4*)(x + (long long)row * D_);
    float ss = 0.f;
    float4 xv[2];
    #pragma unroll
    for (int c = 0; c < 2; c++) {
        xv[c] = xr[threadIdx.x + c * 256];
        ss += xv[c].x * xv[c].x + xv[c].y * xv[c].y + xv[c].z * xv[c].z + xv[c].w * xv[c].w;
    }
    #pragma unroll
    for (int o = 16; o > 0; o >>= 1) ss += __shfl_xor_sync(0xffffffffu, ss, o);
    __shared__ float sred[8];
    if ((threadIdx.x & 31) == 0) sred[threadIdx.x >> 5] = ss;
    __syncthreads();
    float tot = 0.f;
    #pragma unroll
    for (int i = 0; i < 8; i++) tot += sred[i];
    float sc = rsqrtf(tot / (float)D_ + 1e-6f);
    float4* yr = (float4*)(y + (long long)row * D_);
    const float4* wr = (const float4*)w;
    #pragma unroll
    for (int c = 0; c < 2; c++) {
        float4 wv = wr[threadIdx.x + c * 256];
        float4 r;
        r.x = xv[c].x * sc * wv.x;
        r.y = xv[c].y * sc * wv.y;
        r.z = xv[c].z * sc * wv.z;
        r.w = xv[c].w * sc * wv.w;
        yr[threadIdx.x + c * 256] = r;
    }
}

// ---------------- generic SGEMM: C[M,N] = A[M,K] * B[K,N] (+addend) ----------
// lda = row stride of A (elements). If counts != nullptr: expert mode.
// e = blockIdx.z, M = counts[e], row r maps through list: pair = list[r];
// A row = pair >> aShift; C row = pair.
__global__ __launch_bounds__(256, 2) void sgemm_k(
    const float* __restrict__ A, const float* __restrict__ B,
    float* __restrict__ C, const float* __restrict__ addend,
    int M, int N, int K, int lda,
    const int* __restrict__ counts, const int* __restrict__ listBase,
    int aShift, long long bStride) {
    const int* list = listBase;
    if (counts) {
        int e = blockIdx.z;
        M = counts[e];
        list = listBase + e * T_;
        B += (long long)e * bStride;
    }
    int rowBase = blockIdx.y * 128;
    if (rowBase >= M) return;
    int colBase = blockIdx.x * 128;

    __shared__ float As[8][128];
    __shared__ float Bs[8][128];

    int tid = threadIdx.x;
    // A tile load mapping: row = tid & 127, 4-float chunk = (tid >> 7) * 4
    int arL = tid & 127;
    int ar  = rowBase + arL;
    bool aval = (ar < M);
    int arow;
    if (counts) arow = aval ? (list[ar] >> aShift) : 0;
    else        arow = aval ? ar : 0;
    int aC = (tid >> 7) * 4;
    const float* Ap = A + (long long)arow * lda + aC;
    // B tile load mapping: row = tid >> 5 (0..7), col chunk = (tid & 31) * 4
    const float* Bp = B + (long long)(tid >> 5) * N + colBase + (tid & 31) * 4;
    long long bAdv = 8LL * N;

    int ty = tid >> 4, tx = tid & 15;
    float acc[8][8];
    #pragma unroll
    for (int i = 0; i < 8; i++)
        #pragma unroll
        for (int j = 0; j < 8; j++) acc[i][j] = 0.f;

    for (int k0 = 0; k0 < K; k0 += 8) {
        float4 av = aval ? *(const float4*)Ap : make_float4(0.f, 0.f, 0.f, 0.f);
        float4 bv = *(const float4*)Bp;
        As[aC + 0][arL] = av.x;
        As[aC + 1][arL] = av.y;
        As[aC + 2][arL] = av.z;
        As[aC + 3][arL] = av.w;
        *(float4*)&Bs[tid >> 5][(tid & 31) * 4] = bv;
        __syncthreads();
        #pragma unroll
        for (int kk = 0; kk < 8; kk++) {
            float a0[4], a1[4], b0[4], b1[4];
            *(float4*)a0 = *(const float4*)&As[kk][ty * 4];
            *(float4*)a1 = *(const float4*)&As[kk][64 + ty * 4];
            *(float4*)b0 = *(const float4*)&Bs[kk][tx * 4];
            *(float4*)b1 = *(const float4*)&Bs[kk][64 + tx * 4];
            #pragma unroll
            for (int i = 0; i < 4; i++)
                #pragma unroll
                for (int j = 0; j < 4; j++) {
                    acc[i][j]         += a0[i] * b0[j];
                    acc[i][j + 4]     += a0[i] * b1[j];
                    acc[i + 4][j]     += a1[i] * b0[j];
                    acc[i + 4][j + 4] += a1[i] * b1[j];
                }
        }
        __syncthreads();
        Ap += 8;
        Bp += bAdv;
    }

    // epilogue
    #pragma unroll
    for (int ih = 0; ih < 2; ih++) {
        #pragma unroll
        for (int i = 0; i < 4; i++) {
            int rl = ih * 64 + ty * 4 + i;
            int r  = rowBase + rl;
            if (r >= M) continue;
            long long crow = counts ? (long long)list[r] : (long long)r;
            float* Cp = C + crow * N + colBase;
            #pragma unroll
            for (int jh = 0; jh < 2; jh++) {
                float4 res;
                res.x = acc[ih * 4 + i][jh * 4 + 0];
                res.y = acc[ih * 4 + i][jh * 4 + 1];
                res.z = acc[ih * 4 + i][jh * 4 + 2];
                res.w = acc[ih * 4 + i][jh * 4 + 3];
                if (addend) {
                    float4 ad = *(const float4*)(addend + crow * N + colBase + jh * 64 + tx * 4);
                    res.x += ad.x; res.y += ad.y; res.z += ad.z; res.w += ad.w;
                }
                *(float4*)(Cp + jh * 64 + tx * 4) = res;
            }
        }
    }
}

// ---------------- per-head RMSNorm + RoPE (H = ROT_DIM = 128) ----------------
__global__ __launch_bounds__(128) void norm_rope_k(float* __restrict__ x,
                                                   const float* __restrict__ w,
                                                   const float* __restrict__ cosp,
                                                   const float* __restrict__ sinp,
                                                   int nh) {
    int t = blockIdx.x, n = blockIdx.y, d = threadIdx.x;
    float* row = x + ((long long)t * nh + n) * H_;
    float v = row[d];
    float ss = v * v;
    #pragma unroll
    for (int o = 16; o > 0; o >>= 1) ss += __shfl_xor_sync(0xffffffffu, ss, o);
    __shared__ float sr[4];
    if ((d & 31) == 0) sr[d >> 5] = ss;
    __syncthreads();
    float tot = sr[0] + sr[1] + sr[2] + sr[3];
    float xn = v * rsqrtf(tot / 128.f + 1e-6f) * w[d];
    __shared__ float xsh[128];
    xsh[d] = xn;
    __syncthreads();
    float other = xsh[d ^ 64];
    float rot = (d < 64) ? -other : other;
    row[d] = xn * cosp[t * H_ + d] + rot * sinp[t * H_ + d];
}

// ---------------- causal flash attention: block = (t, kv group of 4 heads) ---
__global__ __launch_bounds__(128) void attn_k(const float* __restrict__ q,
                                              const float* __restrict__ k,
                                              const float* __restrict__ v,
                                              float* __restrict__ o) {
    int t  = T_ - 1 - (int)blockIdx.x;   // longest rows first
    int kv = blockIdx.y;
    int d  = threadIdx.x;                // owns dim d for all 4 heads
    int w  = d >> 5, lane = d & 31;
    const float scale = 0.08838834764831845f;   // 128^-0.5

    __shared__ float qs[4][H_];
    __shared__ float ks[32 * 132];
    __shared__ float vs[32 * 132];
    __shared__ float ps[4][32];
    __shared__ float rmax[4], rsum[4];

    #pragma unroll
    for (int h = 0; h < 4; h++)
        qs[h][d] = q[((long long)t * NQ_ + (kv * 4 + h)) * H_ + d] * scale;

    float acc[4] = {0.f, 0.f, 0.f, 0.f};
    float m[4]   = {-1e30f, -1e30f, -1e30f, -1e30f};
    float l[4]   = {0.f, 0.f, 0.f, 0.f};
    __syncthreads();

    for (int s0 = 0; s0 <= t; s0 += 32) {
        int lim = min(32, t - s0 + 1);
        // load K/V tile (zero-fill masked rows so stale smem can't poison AV)
        #pragma unroll 4
        for (int i = 0; i < 32; i++) {
            if (i < lim) {
                long long base = ((long long)(s0 + i) * NKV_ + kv) * H_;
                ks[i * 132 + d] = k[base + d];
                vs[i * 132 + d] = v[base + d];
            } else {
                ks[i * 132 + d] = 0.f;
                vs[i * 132 + d] = 0.f;
            }
        }
        __syncthreads();

        // scores: warp w handles head w, lane handles key `lane`
        float sc = -1e30f;
        if (lane < lim) {
            const float4* kr = (const float4*)&ks[lane * 132];
            const float4* qr = (const float4*)&qs[w][0];
            float s = 0.f;
            #pragma unroll
            for (int j = 0; j < 32; j++) {
                float4 a = kr[j], b = qr[j];
                s += a.x * b.x + a.y * b.y + a.z * b.z + a.w * b.w;
            }
            sc = s;
        }
        float tmax = sc;
        #pragma unroll
        for (int off = 16; off > 0; off >>= 1)
            tmax = fmaxf(tmax, __shfl_xor_sync(0xffffffffu, tmax, off));
        float mth = fmaxf(m[w], tmax);
        float p = (lane < lim) ? expf(sc - mth) : 0.f;
        ps[w][lane] = p;
        float psum = p;
        #pragma unroll
        for (int off = 16; off > 0; off >>= 1)
            psum += __shfl_xor_sync(0xffffffffu, psum, off);
        if (lane == 0) { rmax[w] = tmax; rsum[w] = psum; }
        __syncthreads();

        float corr[4];
        #pragma unroll
        for (int h = 0; h < 4; h++) {
            float mh = fmaxf(m[h], rmax[h]);
            corr[h] = expf(m[h] - mh);
            l[h] = l[h] * corr[h] + rsum[h];
            m[h] = mh;
            acc[h] *= corr[h];
        }
        #pragma unroll 4
        for (int s = 0; s < 32; s++) {
            float vv = vs[s * 132 + d];
            acc[0] += ps[0][s] * vv;
            acc[1] += ps[1][s] * vv;
            acc[2] += ps[2][s] * vv;
            acc[3] += ps[3][s] * vv;
        }
        __syncthreads();
    }
    #pragma unroll
    for (int h = 0; h < 4; h++)
        o[((long long)t * NQ_ + (kv * 4 + h)) * H_ + d] = acc[h] / l[h];
}

// ---------------- router: logits, top-4, softmax weights, expert lists -------
__global__ void zero_cnt_k(int* cnt) { if (threadIdx.x < E_) cnt[threadIdx.x] = 0; }

__global__ __launch_bounds__(128) void router_k(const float* __restrict__ x,
                                                const float* __restrict__ gw,
                                                float* __restrict__ wgt,
                                                int* __restrict__ cnt,
                                                int* __restrict__ list) {
    int t = blockIdx.x, d = threadIdx.x;
    __shared__ float xs[D_];
    for (int i = d; i < D_; i += 128) xs[i] = x[(long long)t * D_ + i];
    __syncthreads();

    // thread d covers K-rows [d*16, d*16+16), all 16 experts
    float part[E_];
    #pragma unroll
    for (int e = 0; e < E_; e++) part[e] = 0.f;
    int j0 = d * 16;
    #pragma unroll 4
    for (int jj = 0; jj < 16; jj++) {
        float xv = xs[j0 + jj];
        const float4* gr = (const float4*)&gw[(long long)(j0 + jj) * E_];
        #pragma unroll
        for (int c = 0; c < 4; c++) {
            float4 g = gr[c];
            part[c * 4 + 0] += xv * g.x;
            part[c * 4 + 1] += xv * g.y;
            part[c * 4 + 2] += xv * g.z;
            part[c * 4 + 3] += xv * g.w;
        }
    }
    __shared__ float psm[128 * E_];
    #pragma unroll
    for (int e = 0; e < E_; e++) psm[d * E_ + e] = part[e];
    __syncthreads();
    __shared__ float lg[E_];
    if (d < E_) {
        float s = 0.f;
        for (int r = 0; r < 128; r++) s += psm[r * E_ + d];
        lg[d] = s;
    }
    __syncthreads();
    if (d == 0) {
        bool used[E_];
        #pragma unroll
        for (int e = 0; e < E_; e++) used[e] = false;
        int idx[4]; float val[4];
        #pragma unroll
        for (int s = 0; s < 4; s++) {
            float best = -1e30f; int bi = 0;
            for (int e = 0; e < E_; e++)
                if (!used[e] && lg[e] > best) { best = lg[e]; bi = e; }
            used[bi] = true; idx[s] = bi; val[s] = best;
        }
        float mm = val[0];
        float sum = 0.f;
        #pragma unroll
        for (int s = 0; s < 4; s++) { val[s] = expf(val[s] - mm); sum += val[s]; }
        #pragma unroll
        for (int s = 0; s < 4; s++) {
            int pair = t * 4 + s;
            wgt[pair] = val[s] / sum;
            int pos = atomicAdd(&cnt[idx[s]], 1);
            list[idx[s] * T_ + pos] = pair;
        }
    }
}

// ---------------- silu(gate) * up * routing_weight (in-place into gate half) -
__global__ __launch_bounds__(256) void silu_k(float* __restrict__ gu,
                                              const float* __restrict__ wgt) {
    int p = blockIdx.x;
    float wv = wgt[p];
    float4* g = (float4*)(gu + (long long)p * 2 * F_);
    const float4* u = (const float4*)(gu + (long long)p * 2 * F_ + F_);
    int f = threadIdx.x;   // 256 threads x 1 float4 = 1024 floats = F_
    float4 gv = g[f], uv = u[f];
    float4 r;
    r.x = wv * uv.x * (gv.x / (1.f + expf(-gv.x)));
    r.y = wv * uv.y * (gv.y / (1.f + expf(-gv.y)));
    r.z = wv * uv.z * (gv.z / (1.f + expf(-gv.z)));
    r.w = wv * uv.w * (gv.w / (1.f + expf(-gv.w)));
    g[f] = r;
}

// ---------------- final residual + sum of 4 expert slots ----------------------
__global__ __launch_bounds__(256) void combine_k(const float* __restrict__ h1,
                                                 const float* __restrict__ part,
                                                 float* __restrict__ out) {
    int t = blockIdx.x;
    const float4* h1r = (const float4*)(h1 + (long long)t * D_);
    float4* outr = (float4*)(out + (long long)t * D_);
    #pragma unroll
    for (int c = 0; c < 2; c++) {
        int i = threadIdx.x + c * 256;
        float4 s = h1r[i];
        #pragma unroll
        for (int slot = 0; slot < 4; slot++) {
            float4 p = *(const float4*)(part + ((long long)t * 4 + slot) * D_ + i * 4);
            s.x += p.x; s.y += p.y; s.z += p.z; s.w += p.w;
        }
        outr[i] = s;
    }
}

// -----------------------------------------------------------------------------
extern "C" void kernel_launch(void* const* d_in, const int* in_sizes, int n_in,
                              void* d_out, int out_size) {
    const float* hidden   = (const float*)d_in[0];
    const float* cosp     = (const float*)d_in[1];
    const float* sinp     = (const float*)d_in[2];
    // d_in[3] = attention_mask (pure causal; implemented analytically)
    const float* input_ln = (const float*)d_in[4];
    const float* post_ln  = (const float*)d_in[5];
    const float* q_w      = (const float*)d_in[6];
    const float* k_w      = (const float*)d_in[7];
    const float* v_w      = (const float*)d_in[8];
    const float* o_w      = (const float*)d_in[9];
    const float* qn_w     = (const float*)d_in[10];
    const float* kn_w     = (const float*)d_in[11];
    const float* gate_w   = (const float*)d_in[12];
    const float* gu_w     = (const float*)d_in[13];
    const float* dn_w     = (const float*)d_in[14];
    float* out = (float*)d_out;

    float *hnorm, *q, *k, *v, *attn, *h1, *h2, *gu, *part, *wgt;
    int *cnt, *list;
    cudaGetSymbolAddress((void**)&hnorm, g_hnorm);
    cudaGetSymbolAddress((void**)&q,     g_q);
    cudaGetSymbolAddress((void**)&k,     g_k);
    cudaGetSymbolAddress((void**)&v,     g_v);
    cudaGetSymbolAddress((void**)&attn,  g_attn);
    cudaGetSymbolAddress((void**)&h1,    g_h1);
    cudaGetSymbolAddress((void**)&h2,    g_h2);
    cudaGetSymbolAddress((void**)&gu,    g_gu);
    cudaGetSymbolAddress((void**)&part,  g_part);
    cudaGetSymbolAddress((void**)&wgt,   g_wgt);
    cudaGetSymbolAddress((void**)&cnt,   g_cnt);
    cudaGetSymbolAddress((void**)&list,  g_list);

    // 1. input RMSNorm
    rmsnorm_k<<<T_, 256>>>(hidden, input_ln, hnorm);
    // 2. Q/K/V projections
    sgemm_k<<<dim3(16, 16), 256>>>(hnorm, q_w, q, nullptr, T_, NQ_ * H_, D_, D_,
                                   nullptr, nullptr, 0, 0);
    sgemm_k<<<dim3(4, 16), 256>>>(hnorm, k_w, k, nullptr, T_, NKV_ * H_, D_, D_,
                                  nullptr, nullptr, 0, 0);
    sgemm_k<<<dim3(4, 16), 256>>>(hnorm, v_w, v, nullptr, T_, NKV_ * H_, D_, D_,
                                  nullptr, nullptr, 0, 0);
    // 3. per-head RMSNorm + RoPE
    norm_rope_k<<<dim3(T_, NQ_), 128>>>(q, qn_w, cosp, sinp, NQ_);
    norm_rope_k<<<dim3(T_, NKV_), 128>>>(k, kn_w, cosp, sinp, NKV_);
    // 4. causal attention (GQA, 4 q-heads per kv head)
    attn_k<<<dim3(T_, NKV_), 128>>>(q, k, v, attn);
    // 5. O projection + residual
    sgemm_k<<<dim3(16, 16), 256>>>(attn, o_w, h1, hidden, T_, D_, NQ_ * H_, NQ_ * H_,
                                   nullptr, nullptr, 0, 0);
    // 6. post RMSNorm
    rmsnorm_k<<<T_, 256>>>(h1, post_ln, h2);
    // 7. routing (top-4) + expert token lists
    zero_cnt_k<<<1, 32>>>(cnt);
    router_k<<<T_, 128>>>(h2, gate_w, wgt, cnt, list);
    // 8. sparse expert gate_up GEMM (gather A rows by token = pair>>2)
    sgemm_k<<<dim3(16, 16, E_), 256>>>(h2, gu_w, gu, nullptr, 0, 2 * F_, D_, D_,
                                       cnt, list, 2, (long long)D_ * 2 * F_);
    // 9. silu(gate)*up*weight (in place, gate half of g_gu becomes act)
    silu_k<<<NPAIR_, 256>>>(gu, wgt);
    // 10. sparse expert down GEMM (A rows = pair, A stride = 2F over act buffer)
    sgemm_k<<<dim3(16, 16, E_), 256>>>(gu, dn_w, part, nullptr, 0, D_, F_, 2 * F_,
                                       cnt, list, 0, (long long)F_ * D_);
    // 11. residual + sum over 4 slots
    combine_k<<<T_, 256>>>(h1, part, out);
}

// round 9
// speedup vs baseline: 2.4703x; 2.4703x over previous
#include <cuda_runtime.h>
#include <cuda_bf16.h>
#include <math.h>
#include <stdint.h>

// Problem constants (Qwen3-MoE decoder layer)
constexpr int T_   = 2048;
constexpr int D_   = 2048;
constexpr int NQ_  = 16;
constexpr int NKV_ = 4;
constexpr int H_   = 128;
constexpr int E_   = 16;
constexpr int F_   = 1024;
constexpr int NPAIR_ = T_ * 4;       // token * top_k slots
constexpr int QKV_N = 3072;          // 2048 q + 512 k + 512 v

// ---------------- scratch (static device globals; no allocation) -------------
__device__ float g_qkv[(size_t)T_ * QKV_N];
__device__ float g_h1[T_ * D_];
__device__ float g_h2[T_ * D_];
__device__ float g_gu[(size_t)NPAIR_ * 2 * F_];
__device__ float g_part[(size_t)NPAIR_ * D_];
__device__ float g_wgt[NPAIR_];
__device__ int   g_cnt[E_];
__device__ int   g_list[E_ * T_];

// split-precision activations (hi/lo bf16)
__device__ __nv_bfloat16 g_hn_hi[T_ * D_],  g_hn_lo[T_ * D_];
__device__ __nv_bfloat16 g_at_hi[T_ * D_],  g_at_lo[T_ * D_];
__device__ __nv_bfloat16 g_h2_hi[T_ * D_],  g_h2_lo[T_ * D_];
__device__ __nv_bfloat16 g_ac_hi[(size_t)NPAIR_ * F_], g_ac_lo[(size_t)NPAIR_ * F_];

// split-precision transposed weights (K-major rows: [N][K])
__device__ __nv_bfloat16 g_qkvw_hi[(size_t)QKV_N * D_], g_qkvw_lo[(size_t)QKV_N * D_];
__device__ __nv_bfloat16 g_ow_hi[(size_t)D_ * D_],      g_ow_lo[(size_t)D_ * D_];
__device__ __nv_bfloat16 g_guw_hi[(size_t)E_ * 2 * F_ * D_], g_guw_lo[(size_t)E_ * 2 * F_ * D_];
__device__ __nv_bfloat16 g_dnw_hi[(size_t)E_ * D_ * F_],     g_dnw_lo[(size_t)E_ * D_ * F_];

// ---------------- helpers -----------------------------------------------------
__device__ __forceinline__ uint32_t smem_u32(const void* p) {
    uint32_t a;
    asm("{ .reg .u64 t; cvta.to.shared.u64 t, %1; cvt.u32.u64 %0, t; }" : "=r"(a) : "l"(p));
    return a;
}
__device__ __forceinline__ void split2(float v, __nv_bfloat16& hi, __nv_bfloat16& lo) {
    hi = __float2bfloat16(v);
    lo = __float2bfloat16(v - __bfloat162float(hi));
}
__device__ __forceinline__ void ldsm4(uint32_t& r0, uint32_t& r1, uint32_t& r2, uint32_t& r3,
                                      uint32_t addr) {
    asm volatile("ldmatrix.sync.aligned.m8n8.x4.shared.b16 {%0,%1,%2,%3}, [%4];"
                 : "=r"(r0), "=r"(r1), "=r"(r2), "=r"(r3) : "r"(addr));
}
__device__ __forceinline__ void mma16816(float* c, const uint32_t* a, const uint32_t* b) {
    asm volatile(
        "mma.sync.aligned.m16n8k16.row.col.f32.bf16.bf16.f32 "
        "{%0,%1,%2,%3}, {%4,%5,%6,%7}, {%8,%9}, {%0,%1,%2,%3};"
        : "+f"(c[0]), "+f"(c[1]), "+f"(c[2]), "+f"(c[3])
        : "r"(a[0]), "r"(a[1]), "r"(a[2]), "r"(a[3]), "r"(b[0]), "r"(b[1]));
}

// ---------------- mma.sync split-bf16 GEMM: C[M,N] = A[M,K] * B^T -------------
// A: hi/lo bf16 [*, lda] row-major. B: hi/lo bf16 [N][K] K-major.
// Expert mode (counts != null): e=blockIdx.z, M=counts[e], pair=list[r],
// A row = pair >> aShift, C row = pair. C stride = N. Optional fp32 addend.
// Block 256 thr = 8 warps (4 along M x 2 along N); warp tile 32x64; BK=32.
constexpr int APAD = 40;   // bf16 row stride (80 B) -> conflict-free LDSM

__global__ __launch_bounds__(256) void tcgemm_k(
    const __nv_bfloat16* __restrict__ Ahi, const __nv_bfloat16* __restrict__ Alo,
    const __nv_bfloat16* __restrict__ Bhi, const __nv_bfloat16* __restrict__ Blo,
    float* __restrict__ C, const float* __restrict__ addend,
    int M, int N, int K, int lda,
    const int* __restrict__ counts, const int* __restrict__ listBase,
    int aShift, long long bStride) {
    const int* list = listBase;
    if (counts) {
        int e = blockIdx.z;
        M = counts[e];
        list = listBase + e * T_;
        Bhi += (size_t)e * bStride;
        Blo += (size_t)e * bStride;
    }
    int rowBase = blockIdx.y * 128;
    if (rowBase >= M) return;
    int colBase = blockIdx.x * 128;

    __shared__ __nv_bfloat16 sAh[128][APAD], sAl[128][APAD];
    __shared__ __nv_bfloat16 sBh[128][APAD], sBl[128][APAD];

    int tid = threadIdx.x, wid = tid >> 5, lane = tid & 31;
    int wm = wid & 3, wn = wid >> 2;

    // ---- global load mapping: 2 threads per row, 32B (2 x uint4) each -------
    int ldRow = tid >> 1;          // 0..127
    int seg   = tid & 1;           // which 32B half of the 64B k-chunk row
    int ar = rowBase + ldRow;
    bool aval = (ar < M);
    int arow = 0;
    if (aval) arow = counts ? (list[ar] >> aShift) : ar;
    const __nv_bfloat16* pAh = Ahi + (size_t)arow * lda + seg * 16;
    const __nv_bfloat16* pAl = Alo + (size_t)arow * lda + seg * 16;
    const __nv_bfloat16* pBh = Bhi + (size_t)(colBase + ldRow) * K + seg * 16;
    const __nv_bfloat16* pBl = Blo + (size_t)(colBase + ldRow) * K + seg * 16;

    float acc[2][8][4];
    #pragma unroll
    for (int mt = 0; mt < 2; mt++)
        #pragma unroll
        for (int nt = 0; nt < 8; nt++)
            #pragma unroll
            for (int i = 0; i < 4; i++) acc[mt][nt][i] = 0.f;

    // LDSM source addresses (fixed per thread; ks offset added per step)
    uint32_t aAddrH[2], aAddrL[2];
    #pragma unroll
    for (int mt = 0; mt < 2; mt++) {
        int r = wm * 32 + mt * 16 + (lane & 15);
        int cofs = (lane >> 4) * 8;
        aAddrH[mt] = smem_u32(&sAh[r][cofs]);
        aAddrL[mt] = smem_u32(&sAl[r][cofs]);
    }
    uint32_t bAddrH[4], bAddrL[4];
    #pragma unroll
    for (int nt2 = 0; nt2 < 4; nt2++) {
        int r = wn * 64 + nt2 * 16 + ((lane >> 4) << 3) + (lane & 7);
        int cofs = ((lane >> 3) & 1) * 8;
        bAddrH[nt2] = smem_u32(&sBh[r][cofs]);
        bAddrL[nt2] = smem_u32(&sBl[r][cofs]);
    }

    const uint4 z4 = make_uint4(0u, 0u, 0u, 0u);
    uint4 rAh0, rAh1, rAl0, rAl1, rBh0, rBh1, rBl0, rBl1;

    // prefetch chunk 0
    {
        rAh0 = aval ? *(const uint4*)(pAh)     : z4;
        rAh1 = aval ? *(const uint4*)(pAh + 8) : z4;
        rAl0 = aval ? *(const uint4*)(pAl)     : z4;
        rAl1 = aval ? *(const uint4*)(pAl + 8) : z4;
        rBh0 = *(const uint4*)(pBh);
        rBh1 = *(const uint4*)(pBh + 8);
        rBl0 = *(const uint4*)(pBl);
        rBl1 = *(const uint4*)(pBl + 8);
    }

    int nch = K >> 5;
    for (int c = 0; c < nch; c++) {
        // store prefetched regs to smem
        int sc = seg * 16;
        *(uint4*)&sAh[ldRow][sc]     = rAh0;
        *(uint4*)&sAh[ldRow][sc + 8] = rAh1;
        *(uint4*)&sAl[ldRow][sc]     = rAl0;
        *(uint4*)&sAl[ldRow][sc + 8] = rAl1;
        *(uint4*)&sBh[ldRow][sc]     = rBh0;
        *(uint4*)&sBh[ldRow][sc + 8] = rBh1;
        *(uint4*)&sBl[ldRow][sc]     = rBl0;
        *(uint4*)&sBl[ldRow][sc + 8] = rBl1;
        __syncthreads();

        // prefetch next chunk (overlaps with compute below)
        if (c + 1 < nch) {
            int k0 = (c + 1) << 5;
            rAh0 = aval ? *(const uint4*)(pAh + k0)     : z4;
            rAh1 = aval ? *(const uint4*)(pAh + k0 + 8) : z4;
            rAl0 = aval ? *(const uint4*)(pAl + k0)     : z4;
            rAl1 = aval ? *(const uint4*)(pAl + k0 + 8) : z4;
            rBh0 = *(const uint4*)(pBh + k0);
            rBh1 = *(const uint4*)(pBh + k0 + 8);
            rBl0 = *(const uint4*)(pBl + k0);
            rBl1 = *(const uint4*)(pBl + k0 + 8);
        }

        // compute: two k16 steps
        #pragma unroll
        for (int ks = 0; ks < 2; ks++) {
            uint32_t kb = ks * 16 * 2;   // byte offset of k-step inside row
            uint32_t ah[2][4], al[2][4], bh[8][2], bl[8][2];
            #pragma unroll
            for (int mt = 0; mt < 2; mt++) {
                ldsm4(ah[mt][0], ah[mt][1], ah[mt][2], ah[mt][3], aAddrH[mt] + kb);
                ldsm4(al[mt][0], al[mt][1], al[mt][2], al[mt][3], aAddrL[mt] + kb);
            }
            #pragma unroll
            for (int nt2 = 0; nt2 < 4; nt2++) {
                uint32_t t0, t1, t2, t3;
                ldsm4(t0, t1, t2, t3, bAddrH[nt2] + kb);
                bh[nt2 * 2][0] = t0; bh[nt2 * 2][1] = t1;
                bh[nt2 * 2 + 1][0] = t2; bh[nt2 * 2 + 1][1] = t3;
                ldsm4(t0, t1, t2, t3, bAddrL[nt2] + kb);
                bl[nt2 * 2][0] = t0; bl[nt2 * 2][1] = t1;
                bl[nt2 * 2 + 1][0] = t2; bl[nt2 * 2 + 1][1] = t3;
            }
            #pragma unroll
            for (int mt = 0; mt < 2; mt++)
                #pragma unroll
                for (int nt = 0; nt < 8; nt++) {
                    mma16816(acc[mt][nt], ah[mt], bh[nt]);
                    mma16816(acc[mt][nt], ah[mt], bl[nt]);
                    mma16816(acc[mt][nt], al[mt], bh[nt]);
                }
        }
        __syncthreads();
    }

    // ---- epilogue ----
    #pragma unroll
    for (int mt = 0; mt < 2; mt++) {
        #pragma unroll
        for (int half = 0; half < 2; half++) {
            int rl = wm * 32 + mt * 16 + half * 8 + (lane >> 2);
            int r  = rowBase + rl;
            if (r >= M) continue;
            long long crow = counts ? (long long)list[r] : (long long)r;
            float* cp = C + crow * N + colBase + wn * 64 + (lane & 3) * 2;
            const float* ap = addend ? addend + crow * N + colBase + wn * 64 + (lane & 3) * 2
                                     : nullptr;
            #pragma unroll
            for (int nt = 0; nt < 8; nt++) {
                float2 res;
                res.x = acc[mt][nt][half * 2 + 0];
                res.y = acc[mt][nt][half * 2 + 1];
                if (ap) {
                    float2 ad = *(const float2*)(ap + nt * 8);
                    res.x += ad.x; res.y += ad.y;
                }
                *(float2*)(cp + nt * 8) = res;
            }
        }
    }
}

// ---------------- weight transpose + split: src fp32 [K][N] -> dst [N][Kd] ---
__global__ __launch_bounds__(256) void tsplit_k(
    const float* __restrict__ src, __nv_bfloat16* __restrict__ dhi,
    __nv_bfloat16* __restrict__ dlo, int K, int N, int Kd,
    long long srcStride, long long dstStride, int dstRowOff) {
    src += (long long)blockIdx.z * srcStride;
    dhi += (long long)blockIdx.z * dstStride;
    dlo += (long long)blockIdx.z * dstStride;
    int n0 = blockIdx.x * 32, k0 = blockIdx.y * 32;
    __shared__ float tile[32][33];
    int x = threadIdx.x & 31, y = threadIdx.x >> 5;
    for (int i = y; i < 32; i += 8)
        tile[i][x] = src[(long long)(k0 + i) * N + n0 + x];
    __syncthreads();
    for (int row = y; row < 32; row += 8) {
        float v = tile[x][row];
        __nv_bfloat16 hi, lo;
        split2(v, hi, lo);
        long long di = (long long)(dstRowOff + n0 + row) * Kd + k0 + x;
        dhi[di] = hi;
        dlo[di] = lo;
    }
}

// ---------------- RMSNorm: fp32 in -> optional fp32 out + hi/lo bf16 out -----
__global__ __launch_bounds__(256) void rmsnorm_k(const float* __restrict__ x,
                                                 const float* __restrict__ w,
                                                 float* __restrict__ yf,
                                                 __nv_bfloat16* __restrict__ yhi,
                                                 __nv_bfloat16* __restrict__ ylo) {
    int row = blockIdx.x;
    const float4* xr = (const float4*)(x + (long long)row * D_);
    float ss = 0.f;
    float4 xv[2];
    #pragma unroll
    for (int c = 0; c < 2; c++) {
        xv[c] = xr[threadIdx.x + c * 256];
        ss += xv[c].x * xv[c].x + xv[c].y * xv[c].y + xv[c].z * xv[c].z + xv[c].w * xv[c].w;
    }
    #pragma unroll
    for (int o = 16; o > 0; o >>= 1) ss += __shfl_xor_sync(0xffffffffu, ss, o);
    __shared__ float sred[8];
    if ((threadIdx.x & 31) == 0) sred[threadIdx.x >> 5] = ss;
    __syncthreads();
    float tot = 0.f;
    #pragma unroll
    for (int i = 0; i < 8; i++) tot += sred[i];
    float sc = rsqrtf(tot / (float)D_ + 1e-6f);
    const float4* wr = (const float4*)w;
    #pragma unroll
    for (int c = 0; c < 2; c++) {
        int i4 = threadIdx.x + c * 256;
        float4 wv = wr[i4];
        float r[4];
        r[0] = xv[c].x * sc * wv.x;
        r[1] = xv[c].y * sc * wv.y;
        r[2] = xv[c].z * sc * wv.z;
        r[3] = xv[c].w * sc * wv.w;
        if (yf) *(float4*)(yf + (long long)row * D_ + i4 * 4) = *(float4*)r;
        long long base = (long long)row * D_ + i4 * 4;
        #pragma unroll
        for (int u = 0; u < 4; u++) {
            __nv_bfloat16 hi, lo;
            split2(r[u], hi, lo);
            yhi[base + u] = hi;
            ylo[base + u] = lo;
        }
    }
}

// ---------------- per-head RMSNorm + RoPE over rows inside qkv buffer --------
__global__ __launch_bounds__(128) void norm_rope_k(float* __restrict__ x, int stride,
                                                   const float* __restrict__ w,
                                                   const float* __restrict__ cosp,
                                                   const float* __restrict__ sinp) {
    int t = blockIdx.x, n = blockIdx.y, d = threadIdx.x;
    float* row = x + (long long)t * stride + n * H_;
    float v = row[d];
    float ss = v * v;
    #pragma unroll
    for (int o = 16; o > 0; o >>= 1) ss += __shfl_xor_sync(0xffffffffu, ss, o);
    __shared__ float sr[4];
    if ((d & 31) == 0) sr[d >> 5] = ss;
    __syncthreads();
    float tot = sr[0] + sr[1] + sr[2] + sr[3];
    float xn = v * rsqrtf(tot / 128.f + 1e-6f) * w[d];
    __shared__ float xsh[128];
    xsh[d] = xn;
    __syncthreads();
    float other = xsh[d ^ 64];
    float rot = (d < 64) ? -other : other;
    row[d] = xn * cosp[t * H_ + d] + rot * sinp[t * H_ + d];
}

// ---------------- causal flash attention (GQA), bf16 hi/lo output ------------
__global__ __launch_bounds__(128) void attn_k(const float* __restrict__ qkv,
                                              __nv_bfloat16* __restrict__ ohi,
                                              __nv_bfloat16* __restrict__ olo) {
    int t  = T_ - 1 - (int)blockIdx.x;
    int kv = blockIdx.y;
    int d  = threadIdx.x;
    int w  = d >> 5, lane = d & 31;
    const float scale = 0.08838834764831845f;

    __shared__ float qs[4][H_];
    __shared__ float ks[32 * 132];
    __shared__ float vs[32 * 132];
    __shared__ float ps[4][32];
    __shared__ float rmax[4], rsum[4];

    #pragma unroll
    for (int h = 0; h < 4; h++)
        qs[h][d] = qkv[(long long)t * QKV_N + (kv * 4 + h) * H_ + d] * scale;

    float acc[4] = {0.f, 0.f, 0.f, 0.f};
    float m[4]   = {-1e30f, -1e30f, -1e30f, -1e30f};
    float l[4]   = {0.f, 0.f, 0.f, 0.f};
    __syncthreads();

    for (int s0 = 0; s0 <= t; s0 += 32) {
        int lim = min(32, t - s0 + 1);
        #pragma unroll 4
        for (int i = 0; i < 32; i++) {
            if (i < lim) {
                long long base = (long long)(s0 + i) * QKV_N + kv * H_;
                ks[i * 132 + d] = qkv[base + 2048 + d];
                vs[i * 132 + d] = qkv[base + 2560 + d];
            } else {
                ks[i * 132 + d] = 0.f;
                vs[i * 132 + d] = 0.f;
            }
        }
        __syncthreads();

        float sc = -1e30f;
        if (lane < lim) {
            const float4* kr = (const float4*)&ks[lane * 132];
            const float4* qr = (const float4*)&qs[w][0];
            float s = 0.f;
            #pragma unroll
            for (int j = 0; j < 32; j++) {
                float4 a = kr[j], b = qr[j];
                s += a.x * b.x + a.y * b.y + a.z * b.z + a.w * b.w;
            }
            sc = s;
        }
        float tmax = sc;
        #pragma unroll
        for (int off = 16; off > 0; off >>= 1)
            tmax = fmaxf(tmax, __shfl_xor_sync(0xffffffffu, tmax, off));
        float mth = fmaxf(m[w], tmax);
        float p = (lane < lim) ? expf(sc - mth) : 0.f;
        ps[w][lane] = p;
        float psum = p;
        #pragma unroll
        for (int off = 16; off > 0; off >>= 1)
            psum += __shfl_xor_sync(0xffffffffu, psum, off);
        if (lane == 0) { rmax[w] = tmax; rsum[w] = psum; }
        __syncthreads();

        #pragma unroll
        for (int h = 0; h < 4; h++) {
            float mh = fmaxf(m[h], rmax[h]);
            float corr = expf(m[h] - mh);
            l[h] = l[h] * corr + rsum[h];
            m[h] = mh;
            acc[h] *= corr;
        }
        #pragma unroll 4
        for (int s = 0; s < 32; s++) {
            float vv = vs[s * 132 + d];
            acc[0] += ps[0][s] * vv;
            acc[1] += ps[1][s] * vv;
            acc[2] += ps[2][s] * vv;
            acc[3] += ps[3][s] * vv;
        }
        __syncthreads();
    }
    #pragma unroll
    for (int h = 0; h < 4; h++) {
        float v = acc[h] / l[h];
        __nv_bfloat16 hi, lo;
        split2(v, hi, lo);
        long long idx = (long long)t * D_ + (kv * 4 + h) * H_ + d;
        ohi[idx] = hi;
        olo[idx] = lo;
    }
}

// ---------------- router: logits, top-4, softmax weights, expert lists -------
__global__ void zero_cnt_k(int* cnt) { if (threadIdx.x < E_) cnt[threadIdx.x] = 0; }

__global__ __launch_bounds__(128) void router_k(const float* __restrict__ x,
                                                const float* __restrict__ gw,
                                                float* __restrict__ wgt,
                                                int* __restrict__ cnt,
                                                int* __restrict__ list) {
    int t = blockIdx.x, d = threadIdx.x;
    __shared__ float xs[D_];
    for (int i = d; i < D_; i += 128) xs[i] = x[(long long)t * D_ + i];
    __syncthreads();

    float part[E_];
    #pragma unroll
    for (int e = 0; e < E_; e++) part[e] = 0.f;
    int j0 = d * 16;
    #pragma unroll 4
    for (int jj = 0; jj < 16; jj++) {
        float xv = xs[j0 + jj];
        const float4* gr = (const float4*)&gw[(long long)(j0 + jj) * E_];
        #pragma unroll
        for (int c = 0; c < 4; c++) {
            float4 g = gr[c];
            part[c * 4 + 0] += xv * g.x;
            part[c * 4 + 1] += xv * g.y;
            part[c * 4 + 2] += xv * g.z;
            part[c * 4 + 3] += xv * g.w;
        }
    }
    __shared__ float psm[128 * E_];
    #pragma unroll
    for (int e = 0; e < E_; e++) psm[d * E_ + e] = part[e];
    __syncthreads();
    __shared__ float lg[E_];
    if (d < E_) {
        float s = 0.f;
        for (int r = 0; r < 128; r++) s += psm[r * E_ + d];
        lg[d] = s;
    }
    __syncthreads();
    if (d == 0) {
        bool used[E_];
        #pragma unroll
        for (int e = 0; e < E_; e++) used[e] = false;
        int idx[4]; float val[4];
        #pragma unroll
        for (int s = 0; s < 4; s++) {
            float best = -1e30f; int bi = 0;
            for (int e = 0; e < E_; e++)
                if (!used[e] && lg[e] > best) { best = lg[e]; bi = e; }
            used[bi] = true; idx[s] = bi; val[s] = best;
        }
        float mm = val[0];
        float sum = 0.f;
        #pragma unroll
        for (int s = 0; s < 4; s++) { val[s] = expf(val[s] - mm); sum += val[s]; }
        #pragma unroll
        for (int s = 0; s < 4; s++) {
            int pair = t * 4 + s;
            wgt[pair] = val[s] / sum;
            int pos = atomicAdd(&cnt[idx[s]], 1);
            list[idx[s] * T_ + pos] = pair;
        }
    }
}

// ---------------- silu(gate)*up*weight -> hi/lo bf16 act ----------------------
__global__ __launch_bounds__(256) void silu_k(const float* __restrict__ gu,
                                              __nv_bfloat16* __restrict__ ahi,
                                              __nv_bfloat16* __restrict__ alo,
                                              const float* __restrict__ wgt) {
    int p = blockIdx.x;
    float wv = wgt[p];
    const float4* g = (const float4*)(gu + (long long)p * 2 * F_);
    const float4* u = (const float4*)(gu + (long long)p * 2 * F_ + F_);
    int f = threadIdx.x;
    float4 gv = g[f], uv = u[f];
    float r[4];
    r[0] = wv * uv.x * (gv.x / (1.f + expf(-gv.x)));
    r[1] = wv * uv.y * (gv.y / (1.f + expf(-gv.y)));
    r[2] = wv * uv.z * (gv.z / (1.f + expf(-gv.z)));
    r[3] = wv * uv.w * (gv.w / (1.f + expf(-gv.w)));
    long long base = (long long)p * F_ + f * 4;
    #pragma unroll
    for (int u2 = 0; u2 < 4; u2++) {
        __nv_bfloat16 hi, lo;
        split2(r[u2], hi, lo);
        ahi[base + u2] = hi;
        alo[base + u2] = lo;
    }
}

// ---------------- final residual + sum of 4 expert slots ----------------------
__global__ __launch_bounds__(256) void combine_k(const float* __restrict__ h1,
                                                 const float* __restrict__ part,
                                                 float* __restrict__ out) {
    int t = blockIdx.x;
    const float4* h1r = (const float4*)(h1 + (long long)t * D_);
    float4* outr = (float4*)(out + (long long)t * D_);
    #pragma unroll
    for (int c = 0; c < 2; c++) {
        int i = threadIdx.x + c * 256;
        float4 s = h1r[i];
        #pragma unroll
        for (int slot = 0; slot < 4; slot++) {
            float4 p = *(const float4*)(part + ((long long)t * 4 + slot) * D_ + i * 4);
            s.x += p.x; s.y += p.y; s.z += p.z; s.w += p.w;
        }
        outr[i] = s;
    }
}

// -----------------------------------------------------------------------------
extern "C" void kernel_launch(void* const* d_in, const int* in_sizes, int n_in,
                              void* d_out, int out_size) {
    const float* hidden   = (const float*)d_in[0];
    const float* cosp     = (const float*)d_in[1];
    const float* sinp     = (const float*)d_in[2];
    // d_in[3] = attention_mask (pure causal; handled analytically)
    const float* input_ln = (const float*)d_in[4];
    const float* post_ln  = (const float*)d_in[5];
    const float* q_w      = (const float*)d_in[6];
    const float* k_w      = (const float*)d_in[7];
    const float* v_w      = (const float*)d_in[8];
    const float* o_w      = (const float*)d_in[9];
    const float* qn_w     = (const float*)d_in[10];
    const float* kn_w     = (const float*)d_in[11];
    const float* gate_w   = (const float*)d_in[12];
    const float* gu_w     = (const float*)d_in[13];
    const float* dn_w     = (const float*)d_in[14];
    float* out = (float*)d_out;

    float *qkv, *h1, *h2, *gu, *part, *wgt;
    int *cnt, *list;
    __nv_bfloat16 *hnh, *hnl, *ath, *atl, *h2h, *h2l, *ach, *acl;
    __nv_bfloat16 *qkvwh, *qkvwl, *owh, *owl, *guwh, *guwl, *dnwh, *dnwl;
    cudaGetSymbolAddress((void**)&qkv,   g_qkv);
    cudaGetSymbolAddress((void**)&h1,    g_h1);
    cudaGetSymbolAddress((void**)&h2,    g_h2);
    cudaGetSymbolAddress((void**)&gu,    g_gu);
    cudaGetSymbolAddress((void**)&part,  g_part);
    cudaGetSymbolAddress((void**)&wgt,   g_wgt);
    cudaGetSymbolAddress((void**)&cnt,   g_cnt);
    cudaGetSymbolAddress((void**)&list,  g_list);
    cudaGetSymbolAddress((void**)&hnh,   g_hn_hi);  cudaGetSymbolAddress((void**)&hnl, g_hn_lo);
    cudaGetSymbolAddress((void**)&ath,   g_at_hi);  cudaGetSymbolAddress((void**)&atl, g_at_lo);
    cudaGetSymbolAddress((void**)&h2h,   g_h2_hi);  cudaGetSymbolAddress((void**)&h2l, g_h2_lo);
    cudaGetSymbolAddress((void**)&ach,   g_ac_hi);  cudaGetSymbolAddress((void**)&acl, g_ac_lo);
    cudaGetSymbolAddress((void**)&qkvwh, g_qkvw_hi); cudaGetSymbolAddress((void**)&qkvwl, g_qkvw_lo);
    cudaGetSymbolAddress((void**)&owh,   g_ow_hi);   cudaGetSymbolAddress((void**)&owl,   g_ow_lo);
    cudaGetSymbolAddress((void**)&guwh,  g_guw_hi);  cudaGetSymbolAddress((void**)&guwl,  g_guw_lo);
    cudaGetSymbolAddress((void**)&dnwh,  g_dnw_hi);  cudaGetSymbolAddress((void**)&dnwl,  g_dnw_lo);

    // ---- weight conversion + transpose to K-major hi/lo bf16 ----
    tsplit_k<<<dim3(2048 / 32, 2048 / 32), 256>>>(q_w, qkvwh, qkvwl, 2048, 2048, 2048, 0, 0, 0);
    tsplit_k<<<dim3(512 / 32, 2048 / 32), 256>>>(k_w, qkvwh, qkvwl, 2048, 512, 2048, 0, 0, 2048);
    tsplit_k<<<dim3(512 / 32, 2048 / 32), 256>>>(v_w, qkvwh, qkvwl, 2048, 512, 2048, 0, 0, 2560);
    tsplit_k<<<dim3(2048 / 32, 2048 / 32), 256>>>(o_w, owh, owl, 2048, 2048, 2048, 0, 0, 0);
    tsplit_k<<<dim3(2048 / 32, 2048 / 32, E_), 256>>>(gu_w, guwh, guwl, 2048, 2048, 2048,
                                                      2048LL * 2048, 2048LL * 2048, 0);
    tsplit_k<<<dim3(2048 / 32, 1024 / 32, E_), 256>>>(dn_w, dnwh, dnwl, 1024, 2048, 1024,
                                                      1024LL * 2048, 2048LL * 1024, 0);

    // 1. input RMSNorm -> hi/lo
    rmsnorm_k<<<T_, 256>>>(hidden, input_ln, nullptr, hnh, hnl);
    // 2. fused QKV projection (N = 3072)
    tcgemm_k<<<dim3(QKV_N / 128, T_ / 128), 256>>>(
        hnh, hnl, qkvwh, qkvwl, qkv, nullptr, T_, QKV_N, D_, D_, nullptr, nullptr, 0, 0);
    // 3. per-head RMSNorm + RoPE (in place inside qkv)
    norm_rope_k<<<dim3(T_, NQ_), 128>>>(qkv, QKV_N, qn_w, cosp, sinp);
    norm_rope_k<<<dim3(T_, NKV_), 128>>>(qkv + 2048, QKV_N, kn_w, cosp, sinp);
    // 4. causal attention -> hi/lo bf16
    attn_k<<<dim3(T_, NKV_), 128>>>(qkv, ath, atl);
    // 5. O projection + residual
    tcgemm_k<<<dim3(D_ / 128, T_ / 128), 256>>>(
        ath, atl, owh, owl, h1, hidden, T_, D_, D_, D_, nullptr, nullptr, 0, 0);
    // 6. post RMSNorm -> fp32 (router) + hi/lo (expert GEMM)
    rmsnorm_k<<<T_, 256>>>(h1, post_ln, h2, h2h, h2l);
    // 7. routing
    zero_cnt_k<<<1, 32>>>(cnt);
    router_k<<<T_, 128>>>(h2, gate_w, wgt, cnt, list);
    // 8. expert gate_up GEMM (A rows gathered by token)
    tcgemm_k<<<dim3((2 * F_) / 128, 16, E_), 256>>>(
        h2h, h2l, guwh, guwl, gu, nullptr, 0, 2 * F_, D_, D_, cnt, list, 2,
        (long long)2 * F_ * D_);
    // 9. silu(gate)*up*weight -> hi/lo act
    silu_k<<<NPAIR_, 256>>>(gu, ach, acl, wgt);
    // 10. expert down GEMM
    tcgemm_k<<<dim3(D_ / 128, 16, E_), 256>>>(
        ach, acl, dnwh, dnwl, part, nullptr, 0, D_, F_, F_, cnt, list, 0,
        (long long)D_ * F_);
    // 11. residual + sum over 4 slots
    combine_k<<<T_, 256>>>(h1, part, out);
}

// round 12
// speedup vs baseline: 2.5729x; 1.0415x over previous
#include <cuda_runtime.h>
#include <cuda_bf16.h>
#include <math.h>
#include <stdint.h>

// Problem constants (Qwen3-MoE decoder layer)
constexpr int T_   = 2048;
constexpr int D_   = 2048;
constexpr int NQ_  = 16;
constexpr int NKV_ = 4;
constexpr int H_   = 128;
constexpr int E_   = 16;
constexpr int F_   = 1024;
constexpr int NPAIR_ = T_ * 4;       // token * top_k slots
constexpr int QKV_N = 3072;          // 2048 q + 512 k + 512 v

// ---------------- scratch (static device globals; no allocation) -------------
__device__ float g_qkv[(size_t)T_ * QKV_N];
__device__ float g_h1[T_ * D_];
__device__ float g_h2[T_ * D_];
__device__ float g_gu[(size_t)NPAIR_ * 2 * F_];
__device__ float g_part[(size_t)NPAIR_ * D_];
__device__ float g_wgt[NPAIR_];
__device__ int   g_cnt[E_];
__device__ int   g_list[E_ * T_];

// split-precision activations (hi/lo bf16)
__device__ __nv_bfloat16 g_hn_hi[T_ * D_],  g_hn_lo[T_ * D_];
__device__ __nv_bfloat16 g_at_hi[T_ * D_],  g_at_lo[T_ * D_];
__device__ __nv_bfloat16 g_h2_hi[T_ * D_],  g_h2_lo[T_ * D_];
__device__ __nv_bfloat16 g_ac_hi[(size_t)NPAIR_ * F_], g_ac_lo[(size_t)NPAIR_ * F_];

// split-precision transposed weights (K-major rows: [N][K])
__device__ __nv_bfloat16 g_qkvw_hi[(size_t)QKV_N * D_], g_qkvw_lo[(size_t)QKV_N * D_];
__device__ __nv_bfloat16 g_ow_hi[(size_t)D_ * D_],      g_ow_lo[(size_t)D_ * D_];
__device__ __nv_bfloat16 g_guw_hi[(size_t)E_ * 2 * F_ * D_], g_guw_lo[(size_t)E_ * 2 * F_ * D_];
__device__ __nv_bfloat16 g_dnw_hi[(size_t)E_ * D_ * F_],     g_dnw_lo[(size_t)E_ * D_ * F_];

// ---------------- helpers -----------------------------------------------------
__device__ __forceinline__ uint32_t smem_u32(const void* p) {
    uint32_t a;
    asm("{ .reg .u64 t; cvta.to.shared.u64 t, %1; cvt.u32.u64 %0, t; }" : "=r"(a) : "l"(p));
    return a;
}
__device__ __forceinline__ void split2(float v, __nv_bfloat16& hi, __nv_bfloat16& lo) {
    hi = __float2bfloat16(v);
    lo = __float2bfloat16(v - __bfloat162float(hi));
}
__device__ __forceinline__ void ldsm4(uint32_t& r0, uint32_t& r1, uint32_t& r2, uint32_t& r3,
                                      uint32_t addr) {
    asm volatile("ldmatrix.sync.aligned.m8n8.x4.shared.b16 {%0,%1,%2,%3}, [%4];"
                 : "=r"(r0), "=r"(r1), "=r"(r2), "=r"(r3) : "r"(addr));
}
__device__ __forceinline__ void mma16816(float* c, const uint32_t* a, const uint32_t* b) {
    asm volatile(
        "mma.sync.aligned.m16n8k16.row.col.f32.bf16.bf16.f32 "
        "{%0,%1,%2,%3}, {%4,%5,%6,%7}, {%8,%9}, {%0,%1,%2,%3};"
        : "+f"(c[0]), "+f"(c[1]), "+f"(c[2]), "+f"(c[3])
        : "r"(a[0]), "r"(a[1]), "r"(a[2]), "r"(a[3]), "r"(b[0]), "r"(b[1]));
}

// ---------------- mma.sync split-bf16 GEMM: C[M,N] = A[M,K] * B^T -------------
// A: hi/lo bf16 [*, lda] row-major. B: hi/lo bf16 [N][K] K-major.
// Expert mode (counts != null): e=blockIdx.z, M=counts[e], pair=list[r],
// A row = pair >> aShift, C row = pair. C stride = N. Optional fp32 addend.
// Block 256 thr = 8 warps (4 along M x 2 along N); warp tile 32x64; BK=32.
// R9-proven version: static smem, register prefetch, no runtime API calls.
constexpr int APAD = 40;   // bf16 row stride (80 B) -> conflict-free LDSM

__global__ __launch_bounds__(256) void tcgemm_k(
    const __nv_bfloat16* __restrict__ Ahi, const __nv_bfloat16* __restrict__ Alo,
    const __nv_bfloat16* __restrict__ Bhi, const __nv_bfloat16* __restrict__ Blo,
    float* __restrict__ C, const float* __restrict__ addend,
    int M, int N, int K, int lda,
    const int* __restrict__ counts, const int* __restrict__ listBase,
    int aShift, long long bStride) {
    const int* list = listBase;
    if (counts) {
        int e = blockIdx.z;
        M = counts[e];
        list = listBase + e * T_;
        Bhi += (size_t)e * bStride;
        Blo += (size_t)e * bStride;
    }
    int rowBase = blockIdx.y * 128;
    if (rowBase >= M) return;
    int colBase = blockIdx.x * 128;

    __shared__ __nv_bfloat16 sAh[128][APAD], sAl[128][APAD];
    __shared__ __nv_bfloat16 sBh[128][APAD], sBl[128][APAD];

    int tid = threadIdx.x, wid = tid >> 5, lane = tid & 31;
    int wm = wid & 3, wn = wid >> 2;

    // ---- global load mapping: 2 threads per row, 32B (2 x uint4) each -------
    int ldRow = tid >> 1;          // 0..127
    int seg   = tid & 1;           // which 32B half of the 64B k-chunk row
    int ar = rowBase + ldRow;
    bool aval = (ar < M);
    int arow = 0;
    if (aval) arow = counts ? (list[ar] >> aShift) : ar;
    const __nv_bfloat16* pAh = Ahi + (size_t)arow * lda + seg * 16;
    const __nv_bfloat16* pAl = Alo + (size_t)arow * lda + seg * 16;
    const __nv_bfloat16* pBh = Bhi + (size_t)(colBase + ldRow) * K + seg * 16;
    const __nv_bfloat16* pBl = Blo + (size_t)(colBase + ldRow) * K + seg * 16;

    float acc[2][8][4];
    #pragma unroll
    for (int mt = 0; mt < 2; mt++)
        #pragma unroll
        for (int nt = 0; nt < 8; nt++)
            #pragma unroll
            for (int i = 0; i < 4; i++) acc[mt][nt][i] = 0.f;

    // LDSM source addresses (fixed per thread; ks offset added per step)
    uint32_t aAddrH[2], aAddrL[2];
    #pragma unroll
    for (int mt = 0; mt < 2; mt++) {
        int r = wm * 32 + mt * 16 + (lane & 15);
        int cofs = (lane >> 4) * 8;
        aAddrH[mt] = smem_u32(&sAh[r][cofs]);
        aAddrL[mt] = smem_u32(&sAl[r][cofs]);
    }
    uint32_t bAddrH[4], bAddrL[4];
    #pragma unroll
    for (int nt2 = 0; nt2 < 4; nt2++) {
        int r = wn * 64 + nt2 * 16 + ((lane >> 4) << 3) + (lane & 7);
        int cofs = ((lane >> 3) & 1) * 8;
        bAddrH[nt2] = smem_u32(&sBh[r][cofs]);
        bAddrL[nt2] = smem_u32(&sBl[r][cofs]);
    }

    const uint4 z4 = make_uint4(0u, 0u, 0u, 0u);
    uint4 rAh0, rAh1, rAl0, rAl1, rBh0, rBh1, rBl0, rBl1;

    // prefetch chunk 0
    {
        rAh0 = aval ? *(const uint4*)(pAh)     : z4;
        rAh1 = aval ? *(const uint4*)(pAh + 8) : z4;
        rAl0 = aval ? *(const uint4*)(pAl)     : z4;
        rAl1 = aval ? *(const uint4*)(pAl + 8) : z4;
        rBh0 = *(const uint4*)(pBh);
        rBh1 = *(const uint4*)(pBh + 8);
        rBl0 = *(const uint4*)(pBl);
        rBl1 = *(const uint4*)(pBl + 8);
    }

    int nch = K >> 5;
    for (int c = 0; c < nch; c++) {
        // store prefetched regs to smem
        int sc = seg * 16;
        *(uint4*)&sAh[ldRow][sc]     = rAh0;
        *(uint4*)&sAh[ldRow][sc + 8] = rAh1;
        *(uint4*)&sAl[ldRow][sc]     = rAl0;
        *(uint4*)&sAl[ldRow][sc + 8] = rAl1;
        *(uint4*)&sBh[ldRow][sc]     = rBh0;
        *(uint4*)&sBh[ldRow][sc + 8] = rBh1;
        *(uint4*)&sBl[ldRow][sc]     = rBl0;
        *(uint4*)&sBl[ldRow][sc + 8] = rBl1;
        __syncthreads();

        // prefetch next chunk (overlaps with compute below)
        if (c + 1 < nch) {
            int k0 = (c + 1) << 5;
            rAh0 = aval ? *(const uint4*)(pAh + k0)     : z4;
            rAh1 = aval ? *(const uint4*)(pAh + k0 + 8) : z4;
            rAl0 = aval ? *(const uint4*)(pAl + k0)     : z4;
            rAl1 = aval ? *(const uint4*)(pAl + k0 + 8) : z4;
            rBh0 = *(const uint4*)(pBh + k0);
            rBh1 = *(const uint4*)(pBh + k0 + 8);
            rBl0 = *(const uint4*)(pBl + k0);
            rBl1 = *(const uint4*)(pBl + k0 + 8);
        }

        // compute: two k16 steps
        #pragma unroll
        for (int ks = 0; ks < 2; ks++) {
            uint32_t kb = ks * 16 * 2;   // byte offset of k-step inside row
            uint32_t ah[2][4], al[2][4], bh[8][2], bl[8][2];
            #pragma unroll
            for (int mt = 0; mt < 2; mt++) {
                ldsm4(ah[mt][0], ah[mt][1], ah[mt][2], ah[mt][3], aAddrH[mt] + kb);
                ldsm4(al[mt][0], al[mt][1], al[mt][2], al[mt][3], aAddrL[mt] + kb);
            }
            #pragma unroll
            for (int nt2 = 0; nt2 < 4; nt2++) {
                uint32_t t0, t1, t2, t3;
                ldsm4(t0, t1, t2, t3, bAddrH[nt2] + kb);
                bh[nt2 * 2][0] = t0; bh[nt2 * 2][1] = t1;
                bh[nt2 * 2 + 1][0] = t2; bh[nt2 * 2 + 1][1] = t3;
                ldsm4(t0, t1, t2, t3, bAddrL[nt2] + kb);
                bl[nt2 * 2][0] = t0; bl[nt2 * 2][1] = t1;
                bl[nt2 * 2 + 1][0] = t2; bl[nt2 * 2 + 1][1] = t3;
            }
            #pragma unroll
            for (int mt = 0; mt < 2; mt++)
                #pragma unroll
                for (int nt = 0; nt < 8; nt++) {
                    mma16816(acc[mt][nt], ah[mt], bh[nt]);
                    mma16816(acc[mt][nt], ah[mt], bl[nt]);
                    mma16816(acc[mt][nt], al[mt], bh[nt]);
                }
        }
        __syncthreads();
    }

    // ---- epilogue ----
    #pragma unroll
    for (int mt = 0; mt < 2; mt++) {
        #pragma unroll
        for (int half = 0; half < 2; half++) {
            int rl = wm * 32 + mt * 16 + half * 8 + (lane >> 2);
            int r  = rowBase + rl;
            if (r >= M) continue;
            long long crow = counts ? (long long)list[r] : (long long)r;
            float* cp = C + crow * N + colBase + wn * 64 + (lane & 3) * 2;
            const float* ap = addend ? addend + crow * N + colBase + wn * 64 + (lane & 3) * 2
                                     : nullptr;
            #pragma unroll
            for (int nt = 0; nt < 8; nt++) {
                float2 res;
                res.x = acc[mt][nt][half * 2 + 0];
                res.y = acc[mt][nt][half * 2 + 1];
                if (ap) {
                    float2 ad = *(const float2*)(ap + nt * 8);
                    res.x += ad.x; res.y += ad.y;
                }
                *(float2*)(cp + nt * 8) = res;
            }
        }
    }
}

// ---------------- weight transpose + split (vectorized): [K][N] -> [N][Kd] ---
// 64x64 tile; float4 loads; uint4 (8 x bf16) transposed stores.
__global__ __launch_bounds__(256) void tsplit_k(
    const float* __restrict__ src, __nv_bfloat16* __restrict__ dhi,
    __nv_bfloat16* __restrict__ dlo, int K, int N, int Kd,
    long long srcStride, long long dstStride, int dstRowOff) {
    src += (long long)blockIdx.z * srcStride;
    dhi += (long long)blockIdx.z * dstStride;
    dlo += (long long)blockIdx.z * dstStride;
    int n0 = blockIdx.x * 64, k0 = blockIdx.y * 64;
    __shared__ float tile[64][65];
    int tx = threadIdx.x & 15, ty = threadIdx.x >> 4;
    #pragma unroll
    for (int i = 0; i < 64; i += 16) {
        int r = i + ty;
        float4 v = *(const float4*)(src + (long long)(k0 + r) * N + n0 + tx * 4);
        tile[r][tx * 4 + 0] = v.x;
        tile[r][tx * 4 + 1] = v.y;
        tile[r][tx * 4 + 2] = v.z;
        tile[r][tx * 4 + 3] = v.w;
    }
    __syncthreads();
    int kc = (threadIdx.x & 7) * 8;
    #pragma unroll
    for (int nb = 0; nb < 2; nb++) {
        int nl = nb * 32 + (threadIdx.x >> 3);
        __nv_bfloat16 hi8[8], lo8[8];
        #pragma unroll
        for (int i = 0; i < 8; i++) split2(tile[kc + i][nl], hi8[i], lo8[i]);
        long long di = (long long)(dstRowOff + n0 + nl) * Kd + k0 + kc;
        *(uint4*)(dhi + di) = *(uint4*)hi8;
        *(uint4*)(dlo + di) = *(uint4*)lo8;
    }
}

// ---------------- RMSNorm: fp32 in -> optional fp32 out + hi/lo bf16 out -----
__global__ __launch_bounds__(256) void rmsnorm_k(const float* __restrict__ x,
                                                 const float* __restrict__ w,
                                                 float* __restrict__ yf,
                                                 __nv_bfloat16* __restrict__ yhi,
                                                 __nv_bfloat16* __restrict__ ylo) {
    int row = blockIdx.x;
    const float4* xr = (const float4*)(x + (long long)row * D_);
    float ss = 0.f;
    float4 xv[2];
    #pragma unroll
    for (int c = 0; c < 2; c++) {
        xv[c] = xr[threadIdx.x + c * 256];
        ss += xv[c].x * xv[c].x + xv[c].y * xv[c].y + xv[c].z * xv[c].z + xv[c].w * xv[c].w;
    }
    #pragma unroll
    for (int o = 16; o > 0; o >>= 1) ss += __shfl_xor_sync(0xffffffffu, ss, o);
    __shared__ float sred[8];
    if ((threadIdx.x & 31) == 0) sred[threadIdx.x >> 5] = ss;
    __syncthreads();
    float tot = 0.f;
    #pragma unroll
    for (int i = 0; i < 8; i++) tot += sred[i];
    float sc = rsqrtf(tot / (float)D_ + 1e-6f);
    const float4* wr = (const float4*)w;
    #pragma unroll
    for (int c = 0; c < 2; c++) {
        int i4 = threadIdx.x + c * 256;
        float4 wv = wr[i4];
        float r[4];
        r[0] = xv[c].x * sc * wv.x;
        r[1] = xv[c].y * sc * wv.y;
        r[2] = xv[c].z * sc * wv.z;
        r[3] = xv[c].w * sc * wv.w;
        if (yf) *(float4*)(yf + (long long)row * D_ + i4 * 4) = *(float4*)r;
        long long base = (long long)row * D_ + i4 * 4;
        #pragma unroll
        for (int u = 0; u < 4; u++) {
            __nv_bfloat16 hi, lo;
            split2(r[u], hi, lo);
            yhi[base + u] = hi;
            ylo[base + u] = lo;
        }
    }
}

// ---------------- per-head RMSNorm + RoPE over rows inside qkv buffer --------
__global__ __launch_bounds__(128) void norm_rope_k(float* __restrict__ x, int stride,
                                                   const float* __restrict__ w,
                                                   const float* __restrict__ cosp,
                                                   const float* __restrict__ sinp) {
    int t = blockIdx.x, n = blockIdx.y, d = threadIdx.x;
    float* row = x + (long long)t * stride + n * H_;
    float v = row[d];
    float ss = v * v;
    #pragma unroll
    for (int o = 16; o > 0; o >>= 1) ss += __shfl_xor_sync(0xffffffffu, ss, o);
    __shared__ float sr[4];
    if ((d & 31) == 0) sr[d >> 5] = ss;
    __syncthreads();
    float tot = sr[0] + sr[1] + sr[2] + sr[3];
    float xn = v * rsqrtf(tot / 128.f + 1e-6f) * w[d];
    __shared__ float xsh[128];
    xsh[d] = xn;
    __syncthreads();
    float other = xsh[d ^ 64];
    float rot = (d < 64) ? -other : other;
    row[d] = xn * cosp[t * H_ + d] + rot * sinp[t * H_ + d];
}

// ---------------- causal flash attention (GQA), bf16 hi/lo output ------------
__global__ __launch_bounds__(128) void attn_k(const float* __restrict__ qkv,
                                              __nv_bfloat16* __restrict__ ohi,
                                              __nv_bfloat16* __restrict__ olo) {
    int t  = T_ - 1 - (int)blockIdx.x;
    int kv = blockIdx.y;
    int d  = threadIdx.x;
    int w  = d >> 5, lane = d & 31;
    const float scale = 0.08838834764831845f;

    __shared__ float qs[4][H_];
    __shared__ float ks[32 * 132];
    __shared__ float vs[32 * 132];
    __shared__ float ps[4][32];
    __shared__ float rmax[4], rsum[4];

    #pragma unroll
    for (int h = 0; h < 4; h++)
        qs[h][d] = qkv[(long long)t * QKV_N + (kv * 4 + h) * H_ + d] * scale;

    float acc[4] = {0.f, 0.f, 0.f, 0.f};
    float m[4]   = {-1e30f, -1e30f, -1e30f, -1e30f};
    float l[4]   = {0.f, 0.f, 0.f, 0.f};
    __syncthreads();

    for (int s0 = 0; s0 <= t; s0 += 32) {
        int lim = min(32, t - s0 + 1);
        #pragma unroll 4
        for (int i = 0; i < 32; i++) {
            if (i < lim) {
                long long base = (long long)(s0 + i) * QKV_N + kv * H_;
                ks[i * 132 + d] = qkv[base + 2048 + d];
                vs[i * 132 + d] = qkv[base + 2560 + d];
            } else {
                ks[i * 132 + d] = 0.f;
                vs[i * 132 + d] = 0.f;
            }
        }
        __syncthreads();

        float sc = -1e30f;
        if (lane < lim) {
            const float4* kr = (const float4*)&ks[lane * 132];
            const float4* qr = (const float4*)&qs[w][0];
            float s = 0.f;
            #pragma unroll
            for (int j = 0; j < 32; j++) {
                float4 a = kr[j], b = qr[j];
                s += a.x * b.x + a.y * b.y + a.z * b.z + a.w * b.w;
            }
            sc = s;
        }
        float tmax = sc;
        #pragma unroll
        for (int off = 16; off > 0; off >>= 1)
            tmax = fmaxf(tmax, __shfl_xor_sync(0xffffffffu, tmax, off));
        float mth = fmaxf(m[w], tmax);
        float p = (lane < lim) ? expf(sc - mth) : 0.f;
        ps[w][lane] = p;
        float psum = p;
        #pragma unroll
        for (int off = 16; off > 0; off >>= 1)
            psum += __shfl_xor_sync(0xffffffffu, psum, off);
        if (lane == 0) { rmax[w] = tmax; rsum[w] = psum; }
        __syncthreads();

        #pragma unroll
        for (int h = 0; h < 4; h++) {
            float mh = fmaxf(m[h], rmax[h]);
            float corr = expf(m[h] - mh);
            l[h] = l[h] * corr + rsum[h];
            m[h] = mh;
            acc[h] *= corr;
        }
        #pragma unroll 4
        for (int s = 0; s < 32; s++) {
            float vv = vs[s * 132 + d];
            acc[0] += ps[0][s] * vv;
            acc[1] += ps[1][s] * vv;
            acc[2] += ps[2][s] * vv;
            acc[3] += ps[3][s] * vv;
        }
        __syncthreads();
    }
    #pragma unroll
    for (int h = 0; h < 4; h++) {
        float v = acc[h] / l[h];
        __nv_bfloat16 hi, lo;
        split2(v, hi, lo);
        long long idx = (long long)t * D_ + (kv * 4 + h) * H_ + d;
        ohi[idx] = hi;
        olo[idx] = lo;
    }
}

// ---------------- router: logits, top-4, softmax weights, expert lists -------
__global__ void zero_cnt_k(int* cnt) { if (threadIdx.x < E_) cnt[threadIdx.x] = 0; }

__global__ __launch_bounds__(128) void router_k(const float* __restrict__ x,
                                                const float* __restrict__ gw,
                                                float* __restrict__ wgt,
                                                int* __restrict__ cnt,
                                                int* __restrict__ list) {
    int t = blockIdx.x, d = threadIdx.x;
    __shared__ float xs[D_];
    for (int i = d; i < D_; i += 128) xs[i] = x[(long long)t * D_ + i];
    __syncthreads();

    float part[E_];
    #pragma unroll
    for (int e = 0; e < E_; e++) part[e] = 0.f;
    int j0 = d * 16;
    #pragma unroll 4
    for (int jj = 0; jj < 16; jj++) {
        float xv = xs[j0 + jj];
        const float4* gr = (const float4*)&gw[(long long)(j0 + jj) * E_];
        #pragma unroll
        for (int c = 0; c < 4; c++) {
            float4 g = gr[c];
            part[c * 4 + 0] += xv * g.x;
            part[c * 4 + 1] += xv * g.y;
            part[c * 4 + 2] += xv * g.z;
            part[c * 4 + 3] += xv * g.w;
        }
    }
    __shared__ float psm[128 * E_];
    #pragma unroll
    for (int e = 0; e < E_; e++) psm[d * E_ + e] = part[e];
    __syncthreads();
    __shared__ float lg[E_];
    if (d < E_) {
        float s = 0.f;
        for (int r = 0; r < 128; r++) s += psm[r * E_ + d];
        lg[d] = s;
    }
    __syncthreads();
    if (d == 0) {
        bool used[E_];
        #pragma unroll
        for (int e = 0; e < E_; e++) used[e] = false;
        int idx[4]; float val[4];
        #pragma unroll
        for (int s = 0; s < 4; s++) {
            float best = -1e30f; int bi = 0;
            for (int e = 0; e < E_; e++)
                if (!used[e] && lg[e] > best) { best = lg[e]; bi = e; }
            used[bi] = true; idx[s] = bi; val[s] = best;
        }
        float mm = val[0];
        float sum = 0.f;
        #pragma unroll
        for (int s = 0; s < 4; s++) { val[s] = expf(val[s] - mm); sum += val[s]; }
        #pragma unroll
        for (int s = 0; s < 4; s++) {
            int pair = t * 4 + s;
            wgt[pair] = val[s] / sum;
            int pos = atomicAdd(&cnt[idx[s]], 1);
            list[idx[s] * T_ + pos] = pair;
        }
    }
}

// ---------------- silu(gate)*up*weight -> hi/lo bf16 act ----------------------
__global__ __launch_bounds__(256) void silu_k(const float* __restrict__ gu,
                                              __nv_bfloat16* __restrict__ ahi,
                                              __nv_bfloat16* __restrict__ alo,
                                              const float* __restrict__ wgt) {
    int p = blockIdx.x;
    float wv = wgt[p];
    const float4* g = (const float4*)(gu + (long long)p * 2 * F_);
    const float4* u = (const float4*)(gu + (long long)p * 2 * F_ + F_);
    int f = threadIdx.x;
    float4 gv = g[f], uv = u[f];
    float r[4];
    r[0] = wv * uv.x * (gv.x / (1.f + expf(-gv.x)));
    r[1] = wv * uv.y * (gv.y / (1.f + expf(-gv.y)));
    r[2] = wv * uv.z * (gv.z / (1.f + expf(-gv.z)));
    r[3] = wv * uv.w * (gv.w / (1.f + expf(-gv.w)));
    long long base = (long long)p * F_ + f * 4;
    #pragma unroll
    for (int u2 = 0; u2 < 4; u2++) {
        __nv_bfloat16 hi, lo;
        split2(r[u2], hi, lo);
        ahi[base + u2] = hi;
        alo[base + u2] = lo;
    }
}

// ---------------- final residual + sum of 4 expert slots ----------------------
__global__ __launch_bounds__(256) void combine_k(const float* __restrict__ h1,
                                                 const float* __restrict__ part,
                                                 float* __restrict__ out) {
    int t = blockIdx.x;
    const float4* h1r = (const float4*)(h1 + (long long)t * D_);
    float4* outr = (float4*)(out + (long long)t * D_);
    #pragma unroll
    for (int c = 0; c < 2; c++) {
        int i = threadIdx.x + c * 256;
        float4 s = h1r[i];
        #pragma unroll
        for (int slot = 0; slot < 4; slot++) {
            float4 p = *(const float4*)(part + ((long long)t * 4 + slot) * D_ + i * 4);
            s.x += p.x; s.y += p.y; s.z += p.z; s.w += p.w;
        }
        outr[i] = s;
    }
}

// -----------------------------------------------------------------------------
extern "C" void kernel_launch(void* const* d_in, const int* in_sizes, int n_in,
                              void* d_out, int out_size) {
    const float* hidden   = (const float*)d_in[0];
    const float* cosp     = (const float*)d_in[1];
    const float* sinp     = (const float*)d_in[2];
    // d_in[3] = attention_mask (pure causal; handled analytically)
    const float* input_ln = (const float*)d_in[4];
    const float* post_ln  = (const float*)d_in[5];
    const float* q_w      = (const float*)d_in[6];
    const float* k_w      = (const float*)d_in[7];
    const float* v_w      = (const float*)d_in[8];
    const float* o_w      = (const float*)d_in[9];
    const float* qn_w     = (const float*)d_in[10];
    const float* kn_w     = (const float*)d_in[11];
    const float* gate_w   = (const float*)d_in[12];
    const float* gu_w     = (const float*)d_in[13];
    const float* dn_w     = (const float*)d_in[14];
    float* out = (float*)d_out;

    float *qkv, *h1, *h2, *gu, *part, *wgt;
    int *cnt, *list;
    __nv_bfloat16 *hnh, *hnl, *ath, *atl, *h2h, *h2l, *ach, *acl;
    __nv_bfloat16 *qkvwh, *qkvwl, *owh, *owl, *guwh, *guwl, *dnwh, *dnwl;
    cudaGetSymbolAddress((void**)&qkv,   g_qkv);
    cudaGetSymbolAddress((void**)&h1,    g_h1);
    cudaGetSymbolAddress((void**)&h2,    g_h2);
    cudaGetSymbolAddress((void**)&gu,    g_gu);
    cudaGetSymbolAddress((void**)&part,  g_part);
    cudaGetSymbolAddress((void**)&wgt,   g_wgt);
    cudaGetSymbolAddress((void**)&cnt,   g_cnt);
    cudaGetSymbolAddress((void**)&list,  g_list);
    cudaGetSymbolAddress((void**)&hnh,   g_hn_hi);  cudaGetSymbolAddress((void**)&hnl, g_hn_lo);
    cudaGetSymbolAddress((void**)&ath,   g_at_hi);  cudaGetSymbolAddress((void**)&atl, g_at_lo);
    cudaGetSymbolAddress((void**)&h2h,   g_h2_hi);  cudaGetSymbolAddress((void**)&h2l, g_h2_lo);
    cudaGetSymbolAddress((void**)&ach,   g_ac_hi);  cudaGetSymbolAddress((void**)&acl, g_ac_lo);
    cudaGetSymbolAddress((void**)&qkvwh, g_qkvw_hi); cudaGetSymbolAddress((void**)&qkvwl, g_qkvw_lo);
    cudaGetSymbolAddress((void**)&owh,   g_ow_hi);   cudaGetSymbolAddress((void**)&owl,   g_ow_lo);
    cudaGetSymbolAddress((void**)&guwh,  g_guw_hi);  cudaGetSymbolAddress((void**)&guwl,  g_guw_lo);
    cudaGetSymbolAddress((void**)&dnwh,  g_dnw_hi);  cudaGetSymbolAddress((void**)&dnwl,  g_dnw_lo);

    // ---- weight conversion + transpose to K-major hi/lo bf16 (64x64 tiles) --
    tsplit_k<<<dim3(2048 / 64, 2048 / 64), 256>>>(q_w, qkvwh, qkvwl, 2048, 2048, 2048, 0, 0, 0);
    tsplit_k<<<dim3(512 / 64, 2048 / 64), 256>>>(k_w, qkvwh, qkvwl, 2048, 512, 2048, 0, 0, 2048);
    tsplit_k<<<dim3(512 / 64, 2048 / 64), 256>>>(v_w, qkvwh, qkvwl, 2048, 512, 2048, 0, 0, 2560);
    tsplit_k<<<dim3(2048 / 64, 2048 / 64), 256>>>(o_w, owh, owl, 2048, 2048, 2048, 0, 0, 0);
    tsplit_k<<<dim3(2048 / 64, 2048 / 64, E_), 256>>>(gu_w, guwh, guwl, 2048, 2048, 2048,
                                                      2048LL * 2048, 2048LL * 2048, 0);
    tsplit_k<<<dim3(2048 / 64, 1024 / 64, E_), 256>>>(dn_w, dnwh, dnwl, 1024, 2048, 1024,
                                                      1024LL * 2048, 2048LL * 1024, 0);

    // 1. input RMSNorm -> hi/lo
    rmsnorm_k<<<T_, 256>>>(hidden, input_ln, nullptr, hnh, hnl);
    // 2. fused QKV projection (N = 3072)
    tcgemm_k<<<dim3(QKV_N / 128, T_ / 128), 256>>>(
        hnh, hnl, qkvwh, qkvwl, qkv, nullptr, T_, QKV_N, D_, D_, nullptr, nullptr, 0, 0);
    // 3. per-head RMSNorm + RoPE (in place inside qkv)
    norm_rope_k<<<dim3(T_, NQ_), 128>>>(qkv, QKV_N, qn_w, cosp, sinp);
    norm_rope_k<<<dim3(T_, NKV_), 128>>>(qkv + 2048, QKV_N, kn_w, cosp, sinp);
    // 4. causal attention -> hi/lo bf16
    attn_k<<<dim3(T_, NKV_), 128>>>(qkv, ath, atl);
    // 5. O projection + residual
    tcgemm_k<<<dim3(D_ / 128, T_ / 128), 256>>>(
        ath, atl, owh, owl, h1, hidden, T_, D_, D_, D_, nullptr, nullptr, 0, 0);
    // 6. post RMSNorm -> fp32 (router) + hi/lo (expert GEMM)
    rmsnorm_k<<<T_, 256>>>(h1, post_ln, h2, h2h, h2l);
    // 7. routing
    zero_cnt_k<<<1, 32>>>(cnt);
    router_k<<<T_, 128>>>(h2, gate_w, wgt, cnt, list);
    // 8. expert gate_up GEMM (A rows gathered by token)
    tcgemm_k<<<dim3((2 * F_) / 128, 16, E_), 256>>>(
        h2h, h2l, guwh, guwl, gu, nullptr, 0, 2 * F_, D_, D_, cnt, list, 2,
        (long long)2 * F_ * D_);
    // 9. silu(gate)*up*weight -> hi/lo act
    silu_k<<<NPAIR_, 256>>>(gu, ach, acl, wgt);
    // 10. expert down GEMM
    tcgemm_k<<<dim3(D_ / 128, 16, E_), 256>>>(
        ach, acl, dnwh, dnwl, part, nullptr, 0, D_, F_, F_, cnt, list, 0,
        (long long)D_ * F_);
    // 11. residual + sum over 4 slots
    combine_k<<<T_, 256>>>(h1, part, out);
}

// round 13
// speedup vs baseline: 2.8072x; 1.0911x over previous
#include <cuda_runtime.h>
#include <cuda_bf16.h>
#include <math.h>
#include <stdint.h>

// Problem constants (Qwen3-MoE decoder layer)
constexpr int T_   = 2048;
constexpr int D_   = 2048;
constexpr int NQ_  = 16;
constexpr int NKV_ = 4;
constexpr int H_   = 128;
constexpr int E_   = 16;
constexpr int F_   = 1024;
constexpr int NPAIR_ = T_ * 4;       // token * top_k slots
constexpr int QKV_N = 3072;          // 2048 q + 512 k + 512 v

// ---------------- scratch (static device globals; no allocation) -------------
__device__ float g_qkv[(size_t)T_ * QKV_N];
__device__ float g_h1[T_ * D_];
__device__ float g_h2[T_ * D_];
__device__ float g_gu[(size_t)NPAIR_ * 2 * F_];
__device__ float g_part[(size_t)NPAIR_ * D_];
__device__ float g_wgt[NPAIR_];
__device__ int   g_cnt[E_];
__device__ int   g_list[E_ * T_];

// split-precision activations (hi/lo bf16)
__device__ __nv_bfloat16 g_hn_hi[T_ * D_],  g_hn_lo[T_ * D_];
__device__ __nv_bfloat16 g_at_hi[T_ * D_],  g_at_lo[T_ * D_];
__device__ __nv_bfloat16 g_h2_hi[T_ * D_],  g_h2_lo[T_ * D_];
__device__ __nv_bfloat16 g_ac_hi[(size_t)NPAIR_ * F_], g_ac_lo[(size_t)NPAIR_ * F_];

// split-precision transposed weights (K-major rows: [N][K])
__device__ __nv_bfloat16 g_qkvw_hi[(size_t)QKV_N * D_], g_qkvw_lo[(size_t)QKV_N * D_];
__device__ __nv_bfloat16 g_ow_hi[(size_t)D_ * D_],      g_ow_lo[(size_t)D_ * D_];
__device__ __nv_bfloat16 g_guw_hi[(size_t)E_ * 2 * F_ * D_], g_guw_lo[(size_t)E_ * 2 * F_ * D_];
__device__ __nv_bfloat16 g_dnw_hi[(size_t)E_ * D_ * F_],     g_dnw_lo[(size_t)E_ * D_ * F_];

// ---------------- helpers -----------------------------------------------------
__device__ __forceinline__ uint32_t smem_u32(const void* p) {
    uint32_t a;
    asm("{ .reg .u64 t; cvta.to.shared.u64 t, %1; cvt.u32.u64 %0, t; }" : "=r"(a) : "l"(p));
    return a;
}
__device__ __forceinline__ void split2(float v, __nv_bfloat16& hi, __nv_bfloat16& lo) {
    hi = __float2bfloat16(v);
    lo = __float2bfloat16(v - __bfloat162float(hi));
}
__device__ __forceinline__ void ldsm4(uint32_t& r0, uint32_t& r1, uint32_t& r2, uint32_t& r3,
                                      uint32_t addr) {
    asm volatile("ldmatrix.sync.aligned.m8n8.x4.shared.b16 {%0,%1,%2,%3}, [%4];"
                 : "=r"(r0), "=r"(r1), "=r"(r2), "=r"(r3) : "r"(addr));
}
__device__ __forceinline__ void mma16816(float* c, const uint32_t* a, const uint32_t* b) {
    asm volatile(
        "mma.sync.aligned.m16n8k16.row.col.f32.bf16.bf16.f32 "
        "{%0,%1,%2,%3}, {%4,%5,%6,%7}, {%8,%9}, {%0,%1,%2,%3};"
        : "+f"(c[0]), "+f"(c[1]), "+f"(c[2]), "+f"(c[3])
        : "r"(a[0]), "r"(a[1]), "r"(a[2]), "r"(a[3]), "r"(b[0]), "r"(b[1]));
}
// packed f32x2 ops (sm_100-family PTX; FFMA2 rt=2 -> 2x fp32 throughput)
__device__ __forceinline__ unsigned long long pk2(float x, float y) {
    float2 t; t.x = x; t.y = y;
    unsigned long long r;
    memcpy(&r, &t, 8);
    return r;
}
__device__ __forceinline__ float2 upk2(unsigned long long v) {
    float2 t;
    memcpy(&t, &v, 8);
    return t;
}
__device__ __forceinline__ void fma2(unsigned long long& d, unsigned long long a,
                                     unsigned long long b) {
    asm("fma.rn.f32x2 %0, %1, %2, %0;" : "+l"(d) : "l"(a), "l"(b));
}
__device__ __forceinline__ void mul2(unsigned long long& d, unsigned long long a) {
    asm("mul.rn.f32x2 %0, %0, %1;" : "+l"(d) : "l"(a));
}

// ---------------- mma.sync split-bf16 GEMM: C[M,N] = A[M,K] * B^T -------------
// R9-proven: static smem, register prefetch, no runtime API calls.
constexpr int APAD = 40;   // bf16 row stride (80 B) -> conflict-free LDSM

__global__ __launch_bounds__(256) void tcgemm_k(
    const __nv_bfloat16* __restrict__ Ahi, const __nv_bfloat16* __restrict__ Alo,
    const __nv_bfloat16* __restrict__ Bhi, const __nv_bfloat16* __restrict__ Blo,
    float* __restrict__ C, const float* __restrict__ addend,
    int M, int N, int K, int lda,
    const int* __restrict__ counts, const int* __restrict__ listBase,
    int aShift, long long bStride) {
    const int* list = listBase;
    if (counts) {
        int e = blockIdx.z;
        M = counts[e];
        list = listBase + e * T_;
        Bhi += (size_t)e * bStride;
        Blo += (size_t)e * bStride;
    }
    int rowBase = blockIdx.y * 128;
    if (rowBase >= M) return;
    int colBase = blockIdx.x * 128;

    __shared__ __nv_bfloat16 sAh[128][APAD], sAl[128][APAD];
    __shared__ __nv_bfloat16 sBh[128][APAD], sBl[128][APAD];

    int tid = threadIdx.x, wid = tid >> 5, lane = tid & 31;
    int wm = wid & 3, wn = wid >> 2;

    int ldRow = tid >> 1;
    int seg   = tid & 1;
    int ar = rowBase + ldRow;
    bool aval = (ar < M);
    int arow = 0;
    if (aval) arow = counts ? (list[ar] >> aShift) : ar;
    const __nv_bfloat16* pAh = Ahi + (size_t)arow * lda + seg * 16;
    const __nv_bfloat16* pAl = Alo + (size_t)arow * lda + seg * 16;
    const __nv_bfloat16* pBh = Bhi + (size_t)(colBase + ldRow) * K + seg * 16;
    const __nv_bfloat16* pBl = Blo + (size_t)(colBase + ldRow) * K + seg * 16;

    float acc[2][8][4];
    #pragma unroll
    for (int mt = 0; mt < 2; mt++)
        #pragma unroll
        for (int nt = 0; nt < 8; nt++)
            #pragma unroll
            for (int i = 0; i < 4; i++) acc[mt][nt][i] = 0.f;

    uint32_t aAddrH[2], aAddrL[2];
    #pragma unroll
    for (int mt = 0; mt < 2; mt++) {
        int r = wm * 32 + mt * 16 + (lane & 15);
        int cofs = (lane >> 4) * 8;
        aAddrH[mt] = smem_u32(&sAh[r][cofs]);
        aAddrL[mt] = smem_u32(&sAl[r][cofs]);
    }
    uint32_t bAddrH[4], bAddrL[4];
    #pragma unroll
    for (int nt2 = 0; nt2 < 4; nt2++) {
        int r = wn * 64 + nt2 * 16 + ((lane >> 4) << 3) + (lane & 7);
        int cofs = ((lane >> 3) & 1) * 8;
        bAddrH[nt2] = smem_u32(&sBh[r][cofs]);
        bAddrL[nt2] = smem_u32(&sBl[r][cofs]);
    }

    const uint4 z4 = make_uint4(0u, 0u, 0u, 0u);
    uint4 rAh0, rAh1, rAl0, rAl1, rBh0, rBh1, rBl0, rBl1;

    {
        rAh0 = aval ? *(const uint4*)(pAh)     : z4;
        rAh1 = aval ? *(const uint4*)(pAh + 8) : z4;
        rAl0 = aval ? *(const uint4*)(pAl)     : z4;
        rAl1 = aval ? *(const uint4*)(pAl + 8) : z4;
        rBh0 = *(const uint4*)(pBh);
        rBh1 = *(const uint4*)(pBh + 8);
        rBl0 = *(const uint4*)(pBl);
        rBl1 = *(const uint4*)(pBl + 8);
    }

    int nch = K >> 5;
    for (int c = 0; c < nch; c++) {
        int sc = seg * 16;
        *(uint4*)&sAh[ldRow][sc]     = rAh0;
        *(uint4*)&sAh[ldRow][sc + 8] = rAh1;
        *(uint4*)&sAl[ldRow][sc]     = rAl0;
        *(uint4*)&sAl[ldRow][sc + 8] = rAl1;
        *(uint4*)&sBh[ldRow][sc]     = rBh0;
        *(uint4*)&sBh[ldRow][sc + 8] = rBh1;
        *(uint4*)&sBl[ldRow][sc]     = rBl0;
        *(uint4*)&sBl[ldRow][sc + 8] = rBl1;
        __syncthreads();

        if (c + 1 < nch) {
            int k0 = (c + 1) << 5;
            rAh0 = aval ? *(const uint4*)(pAh + k0)     : z4;
            rAh1 = aval ? *(const uint4*)(pAh + k0 + 8) : z4;
            rAl0 = aval ? *(const uint4*)(pAl + k0)     : z4;
            rAl1 = aval ? *(const uint4*)(pAl + k0 + 8) : z4;
            rBh0 = *(const uint4*)(pBh + k0);
            rBh1 = *(const uint4*)(pBh + k0 + 8);
            rBl0 = *(const uint4*)(pBl + k0);
            rBl1 = *(const uint4*)(pBl + k0 + 8);
        }

        #pragma unroll
        for (int ks = 0; ks < 2; ks++) {
            uint32_t kb = ks * 16 * 2;
            uint32_t ah[2][4], al[2][4], bh[8][2], bl[8][2];
            #pragma unroll
            for (int mt = 0; mt < 2; mt++) {
                ldsm4(ah[mt][0], ah[mt][1], ah[mt][2], ah[mt][3], aAddrH[mt] + kb);
                ldsm4(al[mt][0], al[mt][1], al[mt][2], al[mt][3], aAddrL[mt] + kb);
            }
            #pragma unroll
            for (int nt2 = 0; nt2 < 4; nt2++) {
                uint32_t t0, t1, t2, t3;
                ldsm4(t0, t1, t2, t3, bAddrH[nt2] + kb);
                bh[nt2 * 2][0] = t0; bh[nt2 * 2][1] = t1;
                bh[nt2 * 2 + 1][0] = t2; bh[nt2 * 2 + 1][1] = t3;
                ldsm4(t0, t1, t2, t3, bAddrL[nt2] + kb);
                bl[nt2 * 2][0] = t0; bl[nt2 * 2][1] = t1;
                bl[nt2 * 2 + 1][0] = t2; bl[nt2 * 2 + 1][1] = t3;
            }
            #pragma unroll
            for (int mt = 0; mt < 2; mt++)
                #pragma unroll
                for (int nt = 0; nt < 8; nt++) {
                    mma16816(acc[mt][nt], ah[mt], bh[nt]);
                    mma16816(acc[mt][nt], ah[mt], bl[nt]);
                    mma16816(acc[mt][nt], al[mt], bh[nt]);
                }
        }
        __syncthreads();
    }

    #pragma unroll
    for (int mt = 0; mt < 2; mt++) {
        #pragma unroll
        for (int half = 0; half < 2; half++) {
            int rl = wm * 32 + mt * 16 + half * 8 + (lane >> 2);
            int r  = rowBase + rl;
            if (r >= M) continue;
            long long crow = counts ? (long long)list[r] : (long long)r;
            float* cp = C + crow * N + colBase + wn * 64 + (lane & 3) * 2;
            const float* ap = addend ? addend + crow * N + colBase + wn * 64 + (lane & 3) * 2
                                     : nullptr;
            #pragma unroll
            for (int nt = 0; nt < 8; nt++) {
                float2 res;
                res.x = acc[mt][nt][half * 2 + 0];
                res.y = acc[mt][nt][half * 2 + 1];
                if (ap) {
                    float2 ad = *(const float2*)(ap + nt * 8);
                    res.x += ad.x; res.y += ad.y;
                }
                *(float2*)(cp + nt * 8) = res;
            }
        }
    }
}

// ---------------- weight transpose + split (vectorized): [K][N] -> [N][Kd] ---
__global__ __launch_bounds__(256) void tsplit_k(
    const float* __restrict__ src, __nv_bfloat16* __restrict__ dhi,
    __nv_bfloat16* __restrict__ dlo, int K, int N, int Kd,
    long long srcStride, long long dstStride, int dstRowOff) {
    src += (long long)blockIdx.z * srcStride;
    dhi += (long long)blockIdx.z * dstStride;
    dlo += (long long)blockIdx.z * dstStride;
    int n0 = blockIdx.x * 64, k0 = blockIdx.y * 64;
    __shared__ float tile[64][65];
    int tx = threadIdx.x & 15, ty = threadIdx.x >> 4;
    #pragma unroll
    for (int i = 0; i < 64; i += 16) {
        int r = i + ty;
        float4 v = *(const float4*)(src + (long long)(k0 + r) * N + n0 + tx * 4);
        tile[r][tx * 4 + 0] = v.x;
        tile[r][tx * 4 + 1] = v.y;
        tile[r][tx * 4 + 2] = v.z;
        tile[r][tx * 4 + 3] = v.w;
    }
    __syncthreads();
    int kc = (threadIdx.x & 7) * 8;
    #pragma unroll
    for (int nb = 0; nb < 2; nb++) {
        int nl = nb * 32 + (threadIdx.x >> 3);
        __nv_bfloat16 hi8[8], lo8[8];
        #pragma unroll
        for (int i = 0; i < 8; i++) split2(tile[kc + i][nl], hi8[i], lo8[i]);
        long long di = (long long)(dstRowOff + n0 + nl) * Kd + k0 + kc;
        *(uint4*)(dhi + di) = *(uint4*)hi8;
        *(uint4*)(dlo + di) = *(uint4*)lo8;
    }
}

// ---------------- RMSNorm: fp32 in -> optional fp32 out + hi/lo bf16 out -----
__global__ __launch_bounds__(256) void rmsnorm_k(const float* __restrict__ x,
                                                 const float* __restrict__ w,
                                                 float* __restrict__ yf,
                                                 __nv_bfloat16* __restrict__ yhi,
                                                 __nv_bfloat16* __restrict__ ylo) {
    int row = blockIdx.x;
    const float4* xr = (const float4*)(x + (long long)row * D_);
    float ss = 0.f;
    float4 xv[2];
    #pragma unroll
    for (int c = 0; c < 2; c++) {
        xv[c] = xr[threadIdx.x + c * 256];
        ss += xv[c].x * xv[c].x + xv[c].y * xv[c].y + xv[c].z * xv[c].z + xv[c].w * xv[c].w;
    }
    #pragma unroll
    for (int o = 16; o > 0; o >>= 1) ss += __shfl_xor_sync(0xffffffffu, ss, o);
    __shared__ float sred[8];
    if ((threadIdx.x & 31) == 0) sred[threadIdx.x >> 5] = ss;
    __syncthreads();
    float tot = 0.f;
    #pragma unroll
    for (int i = 0; i < 8; i++) tot += sred[i];
    float sc = rsqrtf(tot / (float)D_ + 1e-6f);
    const float4* wr = (const float4*)w;
    #pragma unroll
    for (int c = 0; c < 2; c++) {
        int i4 = threadIdx.x + c * 256;
        float4 wv = wr[i4];
        float r[4];
        r[0] = xv[c].x * sc * wv.x;
        r[1] = xv[c].y * sc * wv.y;
        r[2] = xv[c].z * sc * wv.z;
        r[3] = xv[c].w * sc * wv.w;
        if (yf) *(float4*)(yf + (long long)row * D_ + i4 * 4) = *(float4*)r;
        long long base = (long long)row * D_ + i4 * 4;
        #pragma unroll
        for (int u = 0; u < 4; u++) {
            __nv_bfloat16 hi, lo;
            split2(r[u], hi, lo);
            yhi[base + u] = hi;
            ylo[base + u] = lo;
        }
    }
}

// ---------------- per-head RMSNorm + RoPE over rows inside qkv buffer --------
__global__ __launch_bounds__(128) void norm_rope_k(float* __restrict__ x, int stride,
                                                   const float* __restrict__ w,
                                                   const float* __restrict__ cosp,
                                                   const float* __restrict__ sinp) {
    int t = blockIdx.x, n = blockIdx.y, d = threadIdx.x;
    float* row = x + (long long)t * stride + n * H_;
    float v = row[d];
    float ss = v * v;
    #pragma unroll
    for (int o = 16; o > 0; o >>= 1) ss += __shfl_xor_sync(0xffffffffu, ss, o);
    __shared__ float sr[4];
    if ((d & 31) == 0) sr[d >> 5] = ss;
    __syncthreads();
    float tot = sr[0] + sr[1] + sr[2] + sr[3];
    float xn = v * rsqrtf(tot / 128.f + 1e-6f) * w[d];
    __shared__ float xsh[128];
    xsh[d] = xn;
    __syncthreads();
    float other = xsh[d ^ 64];
    float rot = (d < 64) ? -other : other;
    row[d] = xn * cosp[t * H_ + d] + rot * sinp[t * H_ + d];
}

// ---------------- tiled causal flash attention (GQA), packed f32x2 -----------
// Block = (qtile of 32 tokens, kv head). 256 threads: q-row r = tid>>1 (32 tok
// x 4 heads), half = tid&1 owns 64 of 128 dims. K/V tile 32x128 in smem, loaded
// once per 32 queries (kills the L2 re-read bound of the per-token version).
__global__ __launch_bounds__(256, 1) void attn_k(const float* __restrict__ qkv,
                                                 __nv_bfloat16* __restrict__ ohi,
                                                 __nv_bfloat16* __restrict__ olo) {
    int qt   = (T_ / 32 - 1) - (int)blockIdx.x;   // heaviest tiles first
    int kv   = blockIdx.y;
    int tid  = threadIdx.x;
    int r    = tid >> 1;          // q-row 0..127
    int half = tid & 1;           // dim half
    int tr   = r >> 2;            // token within tile
    int token = qt * 32 + tr;
    int head  = kv * 4 + (r & 3);
    const float scale = 0.08838834764831845f;     // 128^-0.5

    __shared__ float ks[32][132];
    __shared__ float vs[32][132];

    // Q: 64 floats -> 32 packed f32x2, pre-scaled
    unsigned long long q2[32];
    {
        const float4* qp = (const float4*)(qkv + (size_t)token * QKV_N + head * H_ + half * 64);
        #pragma unroll
        for (int i = 0; i < 16; i++) {
            float4 v = qp[i];
            q2[2 * i]     = pk2(v.x * scale, v.y * scale);
            q2[2 * i + 1] = pk2(v.z * scale, v.w * scale);
        }
    }

    unsigned long long acc2[32];
    #pragma unroll
    for (int i = 0; i < 32; i++) acc2[i] = 0ull;
    float m = -1e30f, l = 0.f;

    int lr = tid >> 3, c0 = (tid & 7) * 16;       // K/V tile load mapping
    int nt = qt + 1;
    for (int ti = 0; ti < nt; ti++) {
        int s0 = ti * 32;
        __syncthreads();   // prior tile's compute done before overwrite
        {
            const float4* sk = (const float4*)(qkv + (size_t)(s0 + lr) * QKV_N + 2048 + kv * H_ + c0);
            const float4* sv = (const float4*)(qkv + (size_t)(s0 + lr) * QKV_N + 2560 + kv * H_ + c0);
            float4* dk = (float4*)&ks[lr][c0];
            float4* dv = (float4*)&vs[lr][c0];
            #pragma unroll
            for (int j = 0; j < 4; j++) { dk[j] = sk[j]; dv[j] = sv[j]; }
        }
        __syncthreads();

        int jmax = (ti == nt - 1) ? tr : 31;      // causal mask on diagonal tile

        // scores (packed dot over this thread's 64 dims, then pair-combine)
        float s[32];
        #pragma unroll 4
        for (int j = 0; j < 32; j++) {
            unsigned long long sa = 0ull, sb = 0ull;
            const float4* kr = (const float4*)&ks[j][half * 64];
            #pragma unroll
            for (int i = 0; i < 16; i++) {
                float4 k4 = kr[i];
                fma2(sa, q2[2 * i],     pk2(k4.x, k4.y));
                fma2(sb, q2[2 * i + 1], pk2(k4.z, k4.w));
            }
            float2 fa = upk2(sa), fb = upk2(sb);
            float sx = fa.x + fa.y + fb.x + fb.y;
            sx += __shfl_xor_sync(0xffffffffu, sx, 1);
            s[j] = sx;
        }

        // per-tile online softmax update
        float tmax = -1e30f;
        #pragma unroll
        for (int j = 0; j < 32; j++)
            if (j <= jmax) tmax = fmaxf(tmax, s[j]);
        float mn = fmaxf(m, tmax);
        float corr = __expf(m - mn);
        unsigned long long c2 = pk2(corr, corr);
        #pragma unroll
        for (int i = 0; i < 32; i++) mul2(acc2[i], c2);
        float psum = 0.f;
        #pragma unroll
        for (int j = 0; j < 32; j++) {
            float pj = (j <= jmax) ? __expf(s[j] - mn) : 0.f;
            s[j] = pj;
            psum += pj;
        }
        l = l * corr + psum;
        m = mn;

        // AV accumulate (32 independent packed accumulators)
        #pragma unroll 4
        for (int j = 0; j < 32; j++) {
            if (j > jmax) break;
            unsigned long long p2 = pk2(s[j], s[j]);
            const float4* vr = (const float4*)&vs[j][half * 64];
            #pragma unroll
            for (int i = 0; i < 16; i++) {
                float4 v4 = vr[i];
                fma2(acc2[2 * i],     p2, pk2(v4.x, v4.y));
                fma2(acc2[2 * i + 1], p2, pk2(v4.z, v4.w));
            }
        }
    }

    // output: acc/l -> hi/lo bf16
    float inv = 1.f / l;
    long long base = (long long)token * D_ + head * H_ + half * 64;
    #pragma unroll
    for (int i = 0; i < 32; i++) {
        float2 a = upk2(acc2[i]);
        __nv_bfloat16 h0, l0, h1, l1;
        split2(a.x * inv, h0, l0);
        split2(a.y * inv, h1, l1);
        ohi[base + 2 * i]     = h0;
        olo[base + 2 * i]     = l0;
        ohi[base + 2 * i + 1] = h1;
        olo[base + 2 * i + 1] = l1;
    }
}

// ---------------- router: logits, top-4, softmax weights, expert lists -------
__global__ void zero_cnt_k(int* cnt) { if (threadIdx.x < E_) cnt[threadIdx.x] = 0; }

__global__ __launch_bounds__(128) void router_k(const float* __restrict__ x,
                                                const float* __restrict__ gw,
                                                float* __restrict__ wgt,
                                                int* __restrict__ cnt,
                                                int* __restrict__ list) {
    int t = blockIdx.x, d = threadIdx.x;
    __shared__ float xs[D_];
    for (int i = d; i < D_; i += 128) xs[i] = x[(long long)t * D_ + i];
    __syncthreads();

    float part[E_];
    #pragma unroll
    for (int e = 0; e < E_; e++) part[e] = 0.f;
    int j0 = d * 16;
    #pragma unroll 4
    for (int jj = 0; jj < 16; jj++) {
        float xv = xs[j0 + jj];
        const float4* gr = (const float4*)&gw[(long long)(j0 + jj) * E_];
        #pragma unroll
        for (int c = 0; c < 4; c++) {
            float4 g = gr[c];
            part[c * 4 + 0] += xv * g.x;
            part[c * 4 + 1] += xv * g.y;
            part[c * 4 + 2] += xv * g.z;
            part[c * 4 + 3] += xv * g.w;
        }
    }
    __shared__ float psm[128 * E_];
    #pragma unroll
    for (int e = 0; e < E_; e++) psm[d * E_ + e] = part[e];
    __syncthreads();
    __shared__ float lg[E_];
    if (d < E_) {
        float s = 0.f;
        for (int r = 0; r < 128; r++) s += psm[r * E_ + d];
        lg[d] = s;
    }
    __syncthreads();
    if (d == 0) {
        bool used[E_];
        #pragma unroll
        for (int e = 0; e < E_; e++) used[e] = false;
        int idx[4]; float val[4];
        #pragma unroll
        for (int s = 0; s < 4; s++) {
            float best = -1e30f; int bi = 0;
            for (int e = 0; e < E_; e++)
                if (!used[e] && lg[e] > best) { best = lg[e]; bi = e; }
            used[bi] = true; idx[s] = bi; val[s] = best;
        }
        float mm = val[0];
        float sum = 0.f;
        #pragma unroll
        for (int s = 0; s < 4; s++) { val[s] = expf(val[s] - mm); sum += val[s]; }
        #pragma unroll
        for (int s = 0; s < 4; s++) {
            int pair = t * 4 + s;
            wgt[pair] = val[s] / sum;
            int pos = atomicAdd(&cnt[idx[s]], 1);
            list[idx[s] * T_ + pos] = pair;
        }
    }
}

// ---------------- silu(gate)*up*weight -> hi/lo bf16 act ----------------------
__global__ __launch_bounds__(256) void silu_k(const float* __restrict__ gu,
                                              __nv_bfloat16* __restrict__ ahi,
                                              __nv_bfloat16* __restrict__ alo,
                                              const float* __restrict__ wgt) {
    int p = blockIdx.x;
    float wv = wgt[p];
    const float4* g = (const float4*)(gu + (long long)p * 2 * F_);
    const float4* u = (const float4*)(gu + (long long)p * 2 * F_ + F_);
    int f = threadIdx.x;
    float4 gv = g[f], uv = u[f];
    float r[4];
    r[0] = wv * uv.x * (gv.x / (1.f + __expf(-gv.x)));
    r[1] = wv * uv.y * (gv.y / (1.f + __expf(-gv.y)));
    r[2] = wv * uv.z * (gv.z / (1.f + __expf(-gv.z)));
    r[3] = wv * uv.w * (gv.w / (1.f + __expf(-gv.w)));
    long long base = (long long)p * F_ + f * 4;
    #pragma unroll
    for (int u2 = 0; u2 < 4; u2++) {
        __nv_bfloat16 hi, lo;
        split2(r[u2], hi, lo);
        ahi[base + u2] = hi;
        alo[base + u2] = lo;
    }
}

// ---------------- final residual + sum of 4 expert slots ----------------------
__global__ __launch_bounds__(256) void combine_k(const float* __restrict__ h1,
                                                 const float* __restrict__ part,
                                                 float* __restrict__ out) {
    int t = blockIdx.x;
    const float4* h1r = (const float4*)(h1 + (long long)t * D_);
    float4* outr = (float4*)(out + (long long)t * D_);
    #pragma unroll
    for (int c = 0; c < 2; c++) {
        int i = threadIdx.x + c * 256;
        float4 s = h1r[i];
        #pragma unroll
        for (int slot = 0; slot < 4; slot++) {
            float4 p = *(const float4*)(part + ((long long)t * 4 + slot) * D_ + i * 4);
            s.x += p.x; s.y += p.y; s.z += p.z; s.w += p.w;
        }
        outr[i] = s;
    }
}

// -----------------------------------------------------------------------------
extern "C" void kernel_launch(void* const* d_in, const int* in_sizes, int n_in,
                              void* d_out, int out_size) {
    const float* hidden   = (const float*)d_in[0];
    const float* cosp     = (const float*)d_in[1];
    const float* sinp     = (const float*)d_in[2];
    // d_in[3] = attention_mask (pure causal; handled analytically)
    const float* input_ln = (const float*)d_in[4];
    const float* post_ln  = (const float*)d_in[5];
    const float* q_w      = (const float*)d_in[6];
    const float* k_w      = (const float*)d_in[7];
    const float* v_w      = (const float*)d_in[8];
    const float* o_w      = (const float*)d_in[9];
    const float* qn_w     = (const float*)d_in[10];
    const float* kn_w     = (const float*)d_in[11];
    const float* gate_w   = (const float*)d_in[12];
    const float* gu_w     = (const float*)d_in[13];
    const float* dn_w     = (const float*)d_in[14];
    float* out = (float*)d_out;

    float *qkv, *h1, *h2, *gu, *part, *wgt;
    int *cnt, *list;
    __nv_bfloat16 *hnh, *hnl, *ath, *atl, *h2h, *h2l, *ach, *acl;
    __nv_bfloat16 *qkvwh, *qkvwl, *owh, *owl, *guwh, *guwl, *dnwh, *dnwl;
    cudaGetSymbolAddress((void**)&qkv,   g_qkv);
    cudaGetSymbolAddress((void**)&h1,    g_h1);
    cudaGetSymbolAddress((void**)&h2,    g_h2);
    cudaGetSymbolAddress((void**)&gu,    g_gu);
    cudaGetSymbolAddress((void**)&part,  g_part);
    cudaGetSymbolAddress((void**)&wgt,   g_wgt);
    cudaGetSymbolAddress((void**)&cnt,   g_cnt);
    cudaGetSymbolAddress((void**)&list,  g_list);
    cudaGetSymbolAddress((void**)&hnh,   g_hn_hi);  cudaGetSymbolAddress((void**)&hnl, g_hn_lo);
    cudaGetSymbolAddress((void**)&ath,   g_at_hi);  cudaGetSymbolAddress((void**)&atl, g_at_lo);
    cudaGetSymbolAddress((void**)&h2h,   g_h2_hi);  cudaGetSymbolAddress((void**)&h2l, g_h2_lo);
    cudaGetSymbolAddress((void**)&ach,   g_ac_hi);  cudaGetSymbolAddress((void**)&acl, g_ac_lo);
    cudaGetSymbolAddress((void**)&qkvwh, g_qkvw_hi); cudaGetSymbolAddress((void**)&qkvwl, g_qkvw_lo);
    cudaGetSymbolAddress((void**)&owh,   g_ow_hi);   cudaGetSymbolAddress((void**)&owl,   g_ow_lo);
    cudaGetSymbolAddress((void**)&guwh,  g_guw_hi);  cudaGetSymbolAddress((void**)&guwl,  g_guw_lo);
    cudaGetSymbolAddress((void**)&dnwh,  g_dnw_hi);  cudaGetSymbolAddress((void**)&dnwl,  g_dnw_lo);

    // ---- weight conversion + transpose to K-major hi/lo bf16 (64x64 tiles) --
    tsplit_k<<<dim3(2048 / 64, 2048 / 64), 256>>>(q_w, qkvwh, qkvwl, 2048, 2048, 2048, 0, 0, 0);
    tsplit_k<<<dim3(512 / 64, 2048 / 64), 256>>>(k_w, qkvwh, qkvwl, 2048, 512, 2048, 0, 0, 2048);
    tsplit_k<<<dim3(512 / 64, 2048 / 64), 256>>>(v_w, qkvwh, qkvwl, 2048, 512, 2048, 0, 0, 2560);
    tsplit_k<<<dim3(2048 / 64, 2048 / 64), 256>>>(o_w, owh, owl, 2048, 2048, 2048, 0, 0, 0);
    tsplit_k<<<dim3(2048 / 64, 2048 / 64, E_), 256>>>(gu_w, guwh, guwl, 2048, 2048, 2048,
                                                      2048LL * 2048, 2048LL * 2048, 0);
    tsplit_k<<<dim3(2048 / 64, 1024 / 64, E_), 256>>>(dn_w, dnwh, dnwl, 1024, 2048, 1024,
                                                      1024LL * 2048, 2048LL * 1024, 0);

    // 1. input RMSNorm -> hi/lo
    rmsnorm_k<<<T_, 256>>>(hidden, input_ln, nullptr, hnh, hnl);
    // 2. fused QKV projection (N = 3072)
    tcgemm_k<<<dim3(QKV_N / 128, T_ / 128), 256>>>(
        hnh, hnl, qkvwh, qkvwl, qkv, nullptr, T_, QKV_N, D_, D_, nullptr, nullptr, 0, 0);
    // 3. per-head RMSNorm + RoPE (in place inside qkv)
    norm_rope_k<<<dim3(T_, NQ_), 128>>>(qkv, QKV_N, qn_w, cosp, sinp);
    norm_rope_k<<<dim3(T_, NKV_), 128>>>(qkv + 2048, QKV_N, kn_w, cosp, sinp);
    // 4. tiled causal attention -> hi/lo bf16
    attn_k<<<dim3(T_ / 32, NKV_), 256>>>(qkv, ath, atl);
    // 5. O projection + residual
    tcgemm_k<<<dim3(D_ / 128, T_ / 128), 256>>>(
        ath, atl, owh, owl, h1, hidden, T_, D_, D_, D_, nullptr, nullptr, 0, 0);
    // 6. post RMSNorm -> fp32 (router) + hi/lo (expert GEMM)
    rmsnorm_k<<<T_, 256>>>(h1, post_ln, h2, h2h, h2l);
    // 7. routing
    zero_cnt_k<<<1, 32>>>(cnt);
    router_k<<<T_, 128>>>(h2, gate_w, wgt, cnt, list);
    // 8. expert gate_up GEMM (A rows gathered by token)
    tcgemm_k<<<dim3((2 * F_) / 128, 16, E_), 256>>>(
        h2h, h2l, guwh, guwl, gu, nullptr, 0, 2 * F_, D_, D_, cnt, list, 2,
        (long long)2 * F_ * D_);
    // 9. silu(gate)*up*weight -> hi/lo act
    silu_k<<<NPAIR_, 256>>>(gu, ach, acl, wgt);
    // 10. expert down GEMM
    tcgemm_k<<<dim3(D_ / 128, 16, E_), 256>>>(
        ach, acl, dnwh, dnwl, part, nullptr, 0, D_, F_, F_, cnt, list, 0,
        (long long)D_ * F_);
    // 11. residual + sum over 4 slots
    combine_k<<<T_, 256>>>(h1, part, out);
}

// round 15
// speedup vs baseline: 2.8807x; 1.0262x over previous
#include <cuda_runtime.h>
#include <cuda_bf16.h>
#include <math.h>
#include <stdint.h>

// Problem constants (Qwen3-MoE decoder layer)
constexpr int T_   = 2048;
constexpr int D_   = 2048;
constexpr int NQ_  = 16;
constexpr int NKV_ = 4;
constexpr int H_   = 128;
constexpr int E_   = 16;
constexpr int F_   = 1024;
constexpr int NPAIR_ = T_ * 4;       // token * top_k slots
constexpr int QKV_N = 3072;          // 2048 q + 512 k + 512 v

// ---------------- scratch (static device globals; no allocation) -------------
__device__ float g_qkv[(size_t)T_ * QKV_N];
__device__ float g_h1[T_ * D_];
__device__ float g_h2[T_ * D_];
__device__ float g_gu[(size_t)NPAIR_ * 2 * F_];
__device__ float g_part[(size_t)NPAIR_ * D_];
__device__ float g_wgt[NPAIR_];
__device__ int   g_cnt[E_];
__device__ int   g_list[E_ * T_];

// split-precision activations (hi/lo bf16)
__device__ __nv_bfloat16 g_hn_hi[T_ * D_],  g_hn_lo[T_ * D_];
__device__ __nv_bfloat16 g_at_hi[T_ * D_],  g_at_lo[T_ * D_];
__device__ __nv_bfloat16 g_h2_hi[T_ * D_],  g_h2_lo[T_ * D_];
__device__ __nv_bfloat16 g_ac_hi[(size_t)NPAIR_ * F_], g_ac_lo[(size_t)NPAIR_ * F_];

// ---------------- helpers -----------------------------------------------------
__device__ __forceinline__ uint32_t smem_u32(const void* p) {
    uint32_t a;
    asm("{ .reg .u64 t; cvta.to.shared.u64 t, %1; cvt.u32.u64 %0, t; }" : "=r"(a) : "l"(p));
    return a;
}
__device__ __forceinline__ void split2(float v, __nv_bfloat16& hi, __nv_bfloat16& lo) {
    hi = __float2bfloat16(v);
    lo = __float2bfloat16(v - __bfloat162float(hi));
}
__device__ __forceinline__ void ldsm4(uint32_t& r0, uint32_t& r1, uint32_t& r2, uint32_t& r3,
                                      uint32_t addr) {
    asm volatile("ldmatrix.sync.aligned.m8n8.x4.shared.b16 {%0,%1,%2,%3}, [%4];"
                 : "=r"(r0), "=r"(r1), "=r"(r2), "=r"(r3) : "r"(addr));
}
__device__ __forceinline__ void ldsm4t(uint32_t& r0, uint32_t& r1, uint32_t& r2, uint32_t& r3,
                                       uint32_t addr) {
    asm volatile("ldmatrix.sync.aligned.m8n8.x4.trans.shared.b16 {%0,%1,%2,%3}, [%4];"
                 : "=r"(r0), "=r"(r1), "=r"(r2), "=r"(r3) : "r"(addr));
}
__device__ __forceinline__ void mma16816(float* c, const uint32_t* a, const uint32_t* b) {
    asm volatile(
        "mma.sync.aligned.m16n8k16.row.col.f32.bf16.bf16.f32 "
        "{%0,%1,%2,%3}, {%4,%5,%6,%7}, {%8,%9}, {%0,%1,%2,%3};"
        : "+f"(c[0]), "+f"(c[1]), "+f"(c[2]), "+f"(c[3])
        : "r"(a[0]), "r"(a[1]), "r"(a[2]), "r"(a[3]), "r"(b[0]), "r"(b[1]));
}
// packed f32x2 ops
__device__ __forceinline__ unsigned long long pk2(float x, float y) {
    float2 t; t.x = x; t.y = y;
    unsigned long long r;
    memcpy(&r, &t, 8);
    return r;
}
__device__ __forceinline__ float2 upk2(unsigned long long v) {
    float2 t;
    memcpy(&t, &v, 8);
    return t;
}
__device__ __forceinline__ void fma2(unsigned long long& d, unsigned long long a,
                                     unsigned long long b) {
    asm("fma.rn.f32x2 %0, %1, %2, %0;" : "+l"(d) : "l"(a), "l"(b));
}
__device__ __forceinline__ void mul2(unsigned long long& d, unsigned long long a) {
    asm("mul.rn.f32x2 %0, %0, %1;" : "+l"(d) : "l"(a));
}

// ---------------- fused split-bf16 GEMM: C[M,N] = A[M,K] * W[K,N] -------------
// A: hi/lo bf16 [*, lda] row-major (pre-split by producers).
// W: ORIGINAL fp32 [K][N] (row stride ldb) — split to hi/lo on the fly.
// 3-term split product: AhWh + AhWl + AlWh (error ~2^-17).
// Expert mode (counts != null): e=blockIdx.z, M=counts[e], pair=list[r],
// A row = pair >> aShift, C row = pair. C: row stride ldc, col offset cOff.
// Block 256 thr = 8 warps (4 M x 2 N); warp tile 32x64; BK=32; static smem.
constexpr int APAD = 40;    // A smem: 80B rows, conflict-free LDSM
constexpr int BPAD = 136;   // B smem: [32][136] bf16 (272B rows) for ldsm.trans

__global__ __launch_bounds__(256) void tcgemm_k(
    const __nv_bfloat16* __restrict__ Ahi, const __nv_bfloat16* __restrict__ Alo,
    const float* __restrict__ W,
    float* __restrict__ C, const float* __restrict__ addend,
    int M, int K, int lda, int ldb, int ldc, int cOff,
    const int* __restrict__ counts, const int* __restrict__ listBase,
    int aShift, long long bStride) {
    const int* list = listBase;
    if (counts) {
        int e = blockIdx.z;
        M = counts[e];
        list = listBase + e * T_;
        W += (size_t)e * bStride;
    }
    int rowBase = blockIdx.y * 128;
    if (rowBase >= M) return;
    int colBase = blockIdx.x * 128;

    __shared__ __nv_bfloat16 sAh[128][APAD], sAl[128][APAD];
    __shared__ __nv_bfloat16 sBh[32][BPAD], sBl[32][BPAD];

    int tid = threadIdx.x, wid = tid >> 5, lane = tid & 31;
    int wm = wid & 3, wn = wid >> 2;

    // ---- A global load mapping: 2 threads per row, 32B each -----------------
    int ldRow = tid >> 1;
    int seg   = tid & 1;
    int ar = rowBase + ldRow;
    bool aval = (ar < M);
    int arow = 0;
    if (aval) arow = counts ? (list[ar] >> aShift) : ar;
    const __nv_bfloat16* pAh = Ahi + (size_t)arow * lda + seg * 16;
    const __nv_bfloat16* pAl = Alo + (size_t)arow * lda + seg * 16;

    // ---- B global load mapping: thread t -> k-row t>>3, float4 col (t&7)+8g -
    int bkRow = tid >> 3;          // 0..31
    int bf4   = tid & 7;           // base float4 index; +8g, g=0..3
    const float* pB = W + (size_t)bkRow * ldb + colBase + bf4 * 4;

    float acc[2][8][4];
    #pragma unroll
    for (int mt = 0; mt < 2; mt++)
        #pragma unroll
        for (int nt = 0; nt < 8; nt++)
            #pragma unroll
            for (int i = 0; i < 4; i++) acc[mt][nt][i] = 0.f;

    // A LDSM addresses (proven mapping)
    uint32_t aAddrH[2], aAddrL[2];
    #pragma unroll
    for (int mt = 0; mt < 2; mt++) {
        int r = wm * 32 + mt * 16 + (lane & 15);
        int cofs = (lane >> 4) * 8;
        aAddrH[mt] = smem_u32(&sAh[r][cofs]);
        aAddrL[mt] = smem_u32(&sAl[r][cofs]);
    }
    // B LDSM.trans addresses: lane -> k = lane&15, n = n0 + 8*(lane>>4)
    uint32_t bAddrH[4], bAddrL[4];
    #pragma unroll
    for (int nt2 = 0; nt2 < 4; nt2++) {
        int kk = lane & 15;
        int nn = wn * 64 + nt2 * 16 + 8 * (lane >> 4);
        bAddrH[nt2] = smem_u32(&sBh[kk][nn]);
        bAddrL[nt2] = smem_u32(&sBl[kk][nn]);
    }

    const uint4 z4 = make_uint4(0u, 0u, 0u, 0u);
    uint4 rAh0, rAh1, rAl0, rAl1;
    float4 rB[4];

    // prefetch chunk 0
    rAh0 = aval ? *(const uint4*)(pAh)     : z4;
    rAh1 = aval ? *(const uint4*)(pAh + 8) : z4;
    rAl0 = aval ? *(const uint4*)(pAl)     : z4;
    rAl1 = aval ? *(const uint4*)(pAl + 8) : z4;
    #pragma unroll
    for (int g = 0; g < 4; g++) rB[g] = *(const float4*)(pB + g * 32);

    int nch = K >> 5;
    for (int c = 0; c < nch; c++) {
        // store prefetched A
        int sc = seg * 16;
        *(uint4*)&sAh[ldRow][sc]     = rAh0;
        *(uint4*)&sAh[ldRow][sc + 8] = rAh1;
        *(uint4*)&sAl[ldRow][sc]     = rAl0;
        *(uint4*)&sAl[ldRow][sc + 8] = rAl1;
        // store prefetched B (split fp32 -> hi/lo)
        #pragma unroll
        for (int g = 0; g < 4; g++) {
            __nv_bfloat16 h4[4], l4[4];
            split2(rB[g].x, h4[0], l4[0]);
            split2(rB[g].y, h4[1], l4[1]);
            split2(rB[g].z, h4[2], l4[2]);
            split2(rB[g].w, h4[3], l4[3]);
            int nn = bf4 * 4 + g * 32;
            *(uint2*)&sBh[bkRow][nn] = *(uint2*)h4;
            *(uint2*)&sBl[bkRow][nn] = *(uint2*)l4;
        }
        __syncthreads();

        // prefetch next chunk (overlaps compute)
        if (c + 1 < nch) {
            int k0 = (c + 1) << 5;
            rAh0 = aval ? *(const uint4*)(pAh + k0)     : z4;
            rAh1 = aval ? *(const uint4*)(pAh + k0 + 8) : z4;
            rAl0 = aval ? *(const uint4*)(pAl + k0)     : z4;
            rAl1 = aval ? *(const uint4*)(pAl + k0 + 8) : z4;
            const float* pB2 = pB + (size_t)k0 * ldb;
            #pragma unroll
            for (int g = 0; g < 4; g++) rB[g] = *(const float4*)(pB2 + g * 32);
        }

        // compute: two k16 steps
        #pragma unroll
        for (int ks = 0; ks < 2; ks++) {
            uint32_t kbA = ks * 32;              // A: 16 bf16 cols = 32B
            uint32_t kbB = ks * 16 * (BPAD * 2); // B: 16 k-rows
            uint32_t ah[2][4], al[2][4], bh[8][2], bl[8][2];
            #pragma unroll
            for (int mt = 0; mt < 2; mt++) {
                ldsm4(ah[mt][0], ah[mt][1], ah[mt][2], ah[mt][3], aAddrH[mt] + kbA);
                ldsm4(al[mt][0], al[mt][1], al[mt][2], al[mt][3], aAddrL[mt] + kbA);
            }
            #pragma unroll
            for (int nt2 = 0; nt2 < 4; nt2++) {
                uint32_t t0, t1, t2, t3;
                ldsm4t(t0, t1, t2, t3, bAddrH[nt2] + kbB);
                bh[nt2 * 2][0] = t0; bh[nt2 * 2][1] = t1;
                bh[nt2 * 2 + 1][0] = t2; bh[nt2 * 2 + 1][1] = t3;
                ldsm4t(t0, t1, t2, t3, bAddrL[nt2] + kbB);
                bl[nt2 * 2][0] = t0; bl[nt2 * 2][1] = t1;
                bl[nt2 * 2 + 1][0] = t2; bl[nt2 * 2 + 1][1] = t3;
            }
            #pragma unroll
            for (int mt = 0; mt < 2; mt++)
                #pragma unroll
                for (int nt = 0; nt < 8; nt++) {
                    mma16816(acc[mt][nt], ah[mt], bh[nt]);
                    mma16816(acc[mt][nt], ah[mt], bl[nt]);
                    mma16816(acc[mt][nt], al[mt], bh[nt]);
                }
        }
        __syncthreads();
    }

    // ---- epilogue ----
    #pragma unroll
    for (int mt = 0; mt < 2; mt++) {
        #pragma unroll
        for (int half = 0; half < 2; half++) {
            int rl = wm * 32 + mt * 16 + half * 8 + (lane >> 2);
            int r  = rowBase + rl;
            if (r >= M) continue;
            long long crow = counts ? (long long)list[r] : (long long)r;
            long long cbase = crow * ldc + cOff + colBase + wn * 64 + (lane & 3) * 2;
            float* cp = C + cbase;
            const float* ap = addend ? addend + cbase : nullptr;
            #pragma unroll
            for (int nt = 0; nt < 8; nt++) {
                float2 res;
                res.x = acc[mt][nt][half * 2 + 0];
                res.y = acc[mt][nt][half * 2 + 1];
                if (ap) {
                    float2 ad = *(const float2*)(ap + nt * 8);
                    res.x += ad.x; res.y += ad.y;
                }
                *(float2*)(cp + nt * 8) = res;
            }
        }
    }
}

// ---------------- RMSNorm: fp32 in -> optional fp32 out + hi/lo bf16 out -----
__global__ __launch_bounds__(256) void rmsnorm_k(const float* __restrict__ x,
                                                 const float* __restrict__ w,
                                                 float* __restrict__ yf,
                                                 __nv_bfloat16* __restrict__ yhi,
                                                 __nv_bfloat16* __restrict__ ylo) {
    int row = blockIdx.x;
    const float4* xr = (const float4*)(x + (long long)row * D_);
    float ss = 0.f;
    float4 xv[2];
    #pragma unroll
    for (int c = 0; c < 2; c++) {
        xv[c] = xr[threadIdx.x + c * 256];
        ss += xv[c].x * xv[c].x + xv[c].y * xv[c].y + xv[c].z * xv[c].z + xv[c].w * xv[c].w;
    }
    #pragma unroll
    for (int o = 16; o > 0; o >>= 1) ss += __shfl_xor_sync(0xffffffffu, ss, o);
    __shared__ float sred[8];
    if ((threadIdx.x & 31) == 0) sred[threadIdx.x >> 5] = ss;
    __syncthreads();
    float tot = 0.f;
    #pragma unroll
    for (int i = 0; i < 8; i++) tot += sred[i];
    float sc = rsqrtf(tot / (float)D_ + 1e-6f);
    const float4* wr = (const float4*)w;
    #pragma unroll
    for (int c = 0; c < 2; c++) {
        int i4 = threadIdx.x + c * 256;
        float4 wv = wr[i4];
        float r[4];
        r[0] = xv[c].x * sc * wv.x;
        r[1] = xv[c].y * sc * wv.y;
        r[2] = xv[c].z * sc * wv.z;
        r[3] = xv[c].w * sc * wv.w;
        if (yf) *(float4*)(yf + (long long)row * D_ + i4 * 4) = *(float4*)r;
        long long base = (long long)row * D_ + i4 * 4;
        #pragma unroll
        for (int u = 0; u < 4; u++) {
            __nv_bfloat16 hi, lo;
            split2(r[u], hi, lo);
            yhi[base + u] = hi;
            ylo[base + u] = lo;
        }
    }
}

// ---------------- per-head RMSNorm + RoPE over rows inside qkv buffer --------
__global__ __launch_bounds__(128) void norm_rope_k(float* __restrict__ x, int stride,
                                                   const float* __restrict__ w,
                                                   const float* __restrict__ cosp,
                                                   const float* __restrict__ sinp) {
    int t = blockIdx.x, n = blockIdx.y, d = threadIdx.x;
    float* row = x + (long long)t * stride + n * H_;
    float v = row[d];
    float ss = v * v;
    #pragma unroll
    for (int o = 16; o > 0; o >>= 1) ss += __shfl_xor_sync(0xffffffffu, ss, o);
    __shared__ float sr[4];
    if ((d & 31) == 0) sr[d >> 5] = ss;
    __syncthreads();
    float tot = sr[0] + sr[1] + sr[2] + sr[3];
    float xn = v * rsqrtf(tot / 128.f + 1e-6f) * w[d];
    __shared__ float xsh[128];
    xsh[d] = xn;
    __syncthreads();
    float other = xsh[d ^ 64];
    float rot = (d < 64) ? -other : other;
    row[d] = xn * cosp[t * H_ + d] + rot * sinp[t * H_ + d];
}

// ---------------- tiled causal flash attention (GQA), packed f32x2 -----------
__global__ __launch_bounds__(256, 1) void attn_k(const float* __restrict__ qkv,
                                                 __nv_bfloat16* __restrict__ ohi,
                                                 __nv_bfloat16* __restrict__ olo) {
    int qt   = (T_ / 32 - 1) - (int)blockIdx.x;
    int kv   = blockIdx.y;
    int tid  = threadIdx.x;
    int r    = tid >> 1;
    int half = tid & 1;
    int tr   = r >> 2;
    int token = qt * 32 + tr;
    int head  = kv * 4 + (r & 3);
    const float scale = 0.08838834764831845f;

    __shared__ float ks[32][132];
    __shared__ float vs[32][132];

    unsigned long long q2[32];
    {
        const float4* qp = (const float4*)(qkv + (size_t)token * QKV_N + head * H_ + half * 64);
        #pragma unroll
        for (int i = 0; i < 16; i++) {
            float4 v = qp[i];
            q2[2 * i]     = pk2(v.x * scale, v.y * scale);
            q2[2 * i + 1] = pk2(v.z * scale, v.w * scale);
        }
    }

    unsigned long long acc2[32];
    #pragma unroll
    for (int i = 0; i < 32; i++) acc2[i] = 0ull;
    float m = -1e30f, l = 0.f;

    int lr = tid >> 3, c0 = (tid & 7) * 16;
    int nt = qt + 1;
    for (int ti = 0; ti < nt; ti++) {
        int s0 = ti * 32;
        __syncthreads();
        {
            const float4* sk = (const float4*)(qkv + (size_t)(s0 + lr) * QKV_N + 2048 + kv * H_ + c0);
            const float4* sv = (const float4*)(qkv + (size_t)(s0 + lr) * QKV_N + 2560 + kv * H_ + c0);
            float4* dk = (float4*)&ks[lr][c0];
            float4* dv = (float4*)&vs[lr][c0];
            #pragma unroll
            for (int j = 0; j < 4; j++) { dk[j] = sk[j]; dv[j] = sv[j]; }
        }
        __syncthreads();

        int jmax = (ti == nt - 1) ? tr : 31;

        float s[32];
        #pragma unroll 4
        for (int j = 0; j < 32; j++) {
            unsigned long long sa = 0ull, sb = 0ull;
            const float4* kr = (const float4*)&ks[j][half * 64];
            #pragma unroll
            for (int i = 0; i < 16; i++) {
                float4 k4 = kr[i];
                fma2(sa, q2[2 * i],     pk2(k4.x, k4.y));
                fma2(sb, q2[2 * i + 1], pk2(k4.z, k4.w));
            }
            float2 fa = upk2(sa), fb = upk2(sb);
            float sx = fa.x + fa.y + fb.x + fb.y;
            sx += __shfl_xor_sync(0xffffffffu, sx, 1);
            s[j] = sx;
        }

        float tmax = -1e30f;
        #pragma unroll
        for (int j = 0; j < 32; j++)
            if (j <= jmax) tmax = fmaxf(tmax, s[j]);
        float mn = fmaxf(m, tmax);
        float corr = __expf(m - mn);
        unsigned long long c2 = pk2(corr, corr);
        #pragma unroll
        for (int i = 0; i < 32; i++) mul2(acc2[i], c2);
        float psum = 0.f;
        #pragma unroll
        for (int j = 0; j < 32; j++) {
            float pj = (j <= jmax) ? __expf(s[j] - mn) : 0.f;
            s[j] = pj;
            psum += pj;
        }
        l = l * corr + psum;
        m = mn;

        #pragma unroll 4
        for (int j = 0; j < 32; j++) {
            if (j > jmax) break;
            unsigned long long p2 = pk2(s[j], s[j]);
            const float4* vr = (const float4*)&vs[j][half * 64];
            #pragma unroll
            for (int i = 0; i < 16; i++) {
                float4 v4 = vr[i];
                fma2(acc2[2 * i],     p2, pk2(v4.x, v4.y));
                fma2(acc2[2 * i + 1], p2, pk2(v4.z, v4.w));
            }
        }
    }

    float inv = 1.f / l;
    long long base = (long long)token * D_ + head * H_ + half * 64;
    #pragma unroll
    for (int i = 0; i < 32; i++) {
        float2 a = upk2(acc2[i]);
        __nv_bfloat16 h0, l0, h1, l1;
        split2(a.x * inv, h0, l0);
        split2(a.y * inv, h1, l1);
        ohi[base + 2 * i]     = h0;
        olo[base + 2 * i]     = l0;
        ohi[base + 2 * i + 1] = h1;
        olo[base + 2 * i + 1] = l1;
    }
}

// ---------------- router: logits, top-4, softmax weights, expert lists -------
__global__ void zero_cnt_k(int* cnt) { if (threadIdx.x < E_) cnt[threadIdx.x] = 0; }

__global__ __launch_bounds__(128) void router_k(const float* __restrict__ x,
                                                const float* __restrict__ gw,
                                                float* __restrict__ wgt,
                                                int* __restrict__ cnt,
                                                int* __restrict__ list) {
    int t = blockIdx.x, d = threadIdx.x;
    __shared__ float xs[D_];
    for (int i = d; i < D_; i += 128) xs[i] = x[(long long)t * D_ + i];
    __syncthreads();

    float part[E_];
    #pragma unroll
    for (int e = 0; e < E_; e++) part[e] = 0.f;
    int j0 = d * 16;
    #pragma unroll 4
    for (int jj = 0; jj < 16; jj++) {
        float xv = xs[j0 + jj];
        const float4* gr = (const float4*)&gw[(long long)(j0 + jj) * E_];
        #pragma unroll
        for (int c = 0; c < 4; c++) {
            float4 g = gr[c];
            part[c * 4 + 0] += xv * g.x;
            part[c * 4 + 1] += xv * g.y;
            part[c * 4 + 2] += xv * g.z;
            part[c * 4 + 3] += xv * g.w;
        }
    }
    __shared__ float psm[128 * E_];
    #pragma unroll
    for (int e = 0; e < E_; e++) psm[d * E_ + e] = part[e];
    __syncthreads();
    __shared__ float lg[E_];
    if (d < E_) {
        float s = 0.f;
        for (int r = 0; r < 128; r++) s += psm[r * E_ + d];
        lg[d] = s;
    }
    __syncthreads();
    if (d == 0) {
        bool used[E_];
        #pragma unroll
        for (int e = 0; e < E_; e++) used[e] = false;
        int idx[4]; float val[4];
        #pragma unroll
        for (int s = 0; s < 4; s++) {
            float best = -1e30f; int bi = 0;
            for (int e = 0; e < E_; e++)
                if (!used[e] && lg[e] > best) { best = lg[e]; bi = e; }
            used[bi] = true; idx[s] = bi; val[s] = best;
        }
        float mm = val[0];
        float sum = 0.f;
        #pragma unroll
        for (int s = 0; s < 4; s++) { val[s] = expf(val[s] - mm); sum += val[s]; }
        #pragma unroll
        for (int s = 0; s < 4; s++) {
            int pair = t * 4 + s;
            wgt[pair] = val[s] / sum;
            int pos = atomicAdd(&cnt[idx[s]], 1);
            list[idx[s] * T_ + pos] = pair;
        }
    }
}

// ---------------- silu(gate)*up*weight -> hi/lo bf16 act ----------------------
__global__ __launch_bounds__(256) void silu_k(const float* __restrict__ gu,
                                              __nv_bfloat16* __restrict__ ahi,
                                              __nv_bfloat16* __restrict__ alo,
                                              const float* __restrict__ wgt) {
    int p = blockIdx.x;
    float wv = wgt[p];
    const float4* g = (const float4*)(gu + (long long)p * 2 * F_);
    const float4* u = (const float4*)(gu + (long long)p * 2 * F_ + F_);
    int f = threadIdx.x;
    float4 gv = g[f], uv = u[f];
    float r[4];
    r[0] = wv * uv.x * (gv.x / (1.f + __expf(-gv.x)));
    r[1] = wv * uv.y * (gv.y / (1.f + __expf(-gv.y)));
    r[2] = wv * uv.z * (gv.z / (1.f + __expf(-gv.z)));
    r[3] = wv * uv.w * (gv.w / (1.f + __expf(-gv.w)));
    long long base = (long long)p * F_ + f * 4;
    #pragma unroll
    for (int u2 = 0; u2 < 4; u2++) {
        __nv_bfloat16 hi, lo;
        split2(r[u2], hi, lo);
        ahi[base + u2] = hi;
        alo[base + u2] = lo;
    }
}

// ---------------- final residual + sum of 4 expert slots ----------------------
__global__ __launch_bounds__(256) void combine_k(const float* __restrict__ h1,
                                                 const float* __restrict__ part,
                                                 float* __restrict__ out) {
    int t = blockIdx.x;
    const float4* h1r = (const float4*)(h1 + (long long)t * D_);
    float4* outr = (float4*)(out + (long long)t * D_);
    #pragma unroll
    for (int c = 0; c < 2; c++) {
        int i = threadIdx.x + c * 256;
        float4 s = h1r[i];
        #pragma unroll
        for (int slot = 0; slot < 4; slot++) {
            float4 p = *(const float4*)(part + ((long long)t * 4 + slot) * D_ + i * 4);
            s.x += p.x; s.y += p.y; s.z += p.z; s.w += p.w;
        }
        outr[i] = s;
    }
}

// -----------------------------------------------------------------------------
extern "C" void kernel_launch(void* const* d_in, const int* in_sizes, int n_in,
                              void* d_out, int out_size) {
    const float* hidden   = (const float*)d_in[0];
    const float* cosp     = (const float*)d_in[1];
    const float* sinp     = (const float*)d_in[2];
    // d_in[3] = attention_mask (pure causal; handled analytically)
    const float* input_ln = (const float*)d_in[4];
    const float* post_ln  = (const float*)d_in[5];
    const float* q_w      = (const float*)d_in[6];
    const float* k_w      = (const float*)d_in[7];
    const float* v_w      = (const float*)d_in[8];
    const float* o_w      = (const float*)d_in[9];
    const float* qn_w     = (const float*)d_in[10];
    const float* kn_w     = (const float*)d_in[11];
    const float* gate_w   = (const float*)d_in[12];
    const float* gu_w     = (const float*)d_in[13];
    const float* dn_w     = (const float*)d_in[14];
    float* out = (float*)d_out;

    float *qkv, *h1, *h2, *gu, *part, *wgt;
    int *cnt, *list;
    __nv_bfloat16 *hnh, *hnl, *ath, *atl, *h2h, *h2l, *ach, *acl;
    cudaGetSymbolAddress((void**)&qkv,   g_qkv);
    cudaGetSymbolAddress((void**)&h1,    g_h1);
    cudaGetSymbolAddress((void**)&h2,    g_h2);
    cudaGetSymbolAddress((void**)&gu,    g_gu);
    cudaGetSymbolAddress((void**)&part,  g_part);
    cudaGetSymbolAddress((void**)&wgt,   g_wgt);
    cudaGetSymbolAddress((void**)&cnt,   g_cnt);
    cudaGetSymbolAddress((void**)&list,  g_list);
    cudaGetSymbolAddress((void**)&hnh,   g_hn_hi);  cudaGetSymbolAddress((void**)&hnl, g_hn_lo);
    cudaGetSymbolAddress((void**)&ath,   g_at_hi);  cudaGetSymbolAddress((void**)&atl, g_at_lo);
    cudaGetSymbolAddress((void**)&h2h,   g_h2_hi);  cudaGetSymbolAddress((void**)&h2l, g_h2_lo);
    cudaGetSymbolAddress((void**)&ach,   g_ac_hi);  cudaGetSymbolAddress((void**)&acl, g_ac_lo);

    // 1. input RMSNorm -> hi/lo
    rmsnorm_k<<<T_, 256>>>(hidden, input_ln, nullptr, hnh, hnl);
    // 2. Q/K/V projections (fused fp32-weight GEMM; outputs into g_qkv slab)
    tcgemm_k<<<dim3(2048 / 128, T_ / 128), 256>>>(
        hnh, hnl, q_w, qkv, nullptr, T_, D_, D_, 2048, QKV_N, 0,
        nullptr, nullptr, 0, 0);
    tcgemm_k<<<dim3(512 / 128, T_ / 128), 256>>>(
        hnh, hnl, k_w, qkv, nullptr, T_, D_, D_, 512, QKV_N, 2048,
        nullptr, nullptr, 0, 0);
    tcgemm_k<<<dim3(512 / 128, T_ / 128), 256>>>(
        hnh, hnl, v_w, qkv, nullptr, T_, D_, D_, 512, QKV_N, 2560,
        nullptr, nullptr, 0, 0);
    // 3. per-head RMSNorm + RoPE (in place inside qkv)
    norm_rope_k<<<dim3(T_, NQ_), 128>>>(qkv, QKV_N, qn_w, cosp, sinp);
    norm_rope_k<<<dim3(T_, NKV_), 128>>>(qkv + 2048, QKV_N, kn_w, cosp, sinp);
    // 4. tiled causal attention -> hi/lo bf16
    attn_k<<<dim3(T_ / 32, NKV_), 256>>>(qkv, ath, atl);
    // 5. O projection + residual
    tcgemm_k<<<dim3(D_ / 128, T_ / 128), 256>>>(
        ath, atl, o_w, h1, hidden, T_, D_, D_, D_, D_, 0,
        nullptr, nullptr, 0, 0);
    // 6. post RMSNorm -> fp32 (router) + hi/lo (expert GEMM)
    rmsnorm_k<<<T_, 256>>>(h1, post_ln, h2, h2h, h2l);
    // 7. routing
    zero_cnt_k<<<1, 32>>>(cnt);
    router_k<<<T_, 128>>>(h2, gate_w, wgt, cnt, list);
    // 8. expert gate_up GEMM (A rows gathered by token; per-expert fp32 W)
    tcgemm_k<<<dim3((2 * F_) / 128, 16, E_), 256>>>(
        h2h, h2l, gu_w, gu, nullptr, 0, D_, D_, 2 * F_, 2 * F_, 0,
        cnt, list, 2, (long long)D_ * 2 * F_);
    // 9. silu(gate)*up*weight -> hi/lo act
    silu_k<<<NPAIR_, 256>>>(gu, ach, acl, wgt);
    // 10. expert down GEMM
    tcgemm_k<<<dim3(D_ / 128, 16, E_), 256>>>(
        ach, acl, dn_w, part, nullptr, 0, F_, F_, D_, D_, 0,
        cnt, list, 0, (long long)F_ * D_);
    // 11. residual + sum over 4 slots
    combine_k<<<T_, 256>>>(h1, part, out);
}